// round 4
// baseline (speedup 1.0000x reference)
#include <cuda_runtime.h>
#include <math.h>

// ---------------- problem constants ----------------
#define cB    32
#define cA    100
#define cD    10000
#define cHID  256
#define cNH   4
#define cOUT  10000
#define cNF   16
#define cE    100
#define cN    100
#define cFEAT 33          // 1 + 2*NFREQ
#define cBA   (cB*cA)     // 3200
#define cSLOTS (cBA*cE)   // 320000
#define cSTEPS 3

// ---------------- scratch (device globals; no allocs allowed) ----------------
__device__ int   g_cnt[cBA];
__device__ int   g_idx[cSLOTS];
__device__ float g_val[cSLOTS];
__device__ float g_feat[(long long)cSLOTS*cFEAT];
__device__ float g_H1 [(long long)cSLOTS*cHID];
__device__ float g_e  [(long long)cSLOTS*cHID];
__device__ float g_c1 [cBA*2*cHID];
__device__ float g_h  [cBA*cHID];
__device__ float g_Qb [cNH*cBA*cHID];
__device__ float g_Kb [cNH*cBA*cHID];
__device__ float g_Vb [cNH*cBA*cHID];
__device__ float g_Hs [cNH*cBA*cHID];   // swish(Hm)
__device__ float g_t1 [cNH*cBA*cHID];
__device__ float g_t2 [cNH*cBA*cHID];

// ---------------- helpers ----------------
__device__ __forceinline__ float swishf(float v) { return v / (1.f + expf(-v)); }

__device__ __forceinline__ float warpSum(float v) {
#pragma unroll
    for (int o = 16; o > 0; o >>= 1) v += __shfl_xor_sync(0xffffffffu, v, o);
    return v;
}
__device__ __forceinline__ float warpMax(float v) {
#pragma unroll
    for (int o = 16; o > 0; o >>= 1) v = fmaxf(v, __shfl_xor_sync(0xffffffffu, v, o));
    return v;
}

// ---------------- 1. ragged gather of nonzeros (stable, ascending) ----------------
// one block per (b,agent); 256 threads scan D=10000, compact first E nonzeros.
__global__ void k_gather(const float* __restrict__ x) {
    int m = blockIdx.x;
    const float* xr = x + (long long)m * cD;
    int tid = threadIdx.x, lane = tid & 31, w = tid >> 5;
    __shared__ int warp_cnt[8];
    __shared__ int s_base;
    if (tid == 0) s_base = 0;
    __syncthreads();
    for (int c0 = 0; c0 < cD; c0 += 256) {
        int i = c0 + tid;
        float v = (i < cD) ? xr[i] : 0.f;
        bool nz = (i < cD) && (v != 0.f);
        unsigned ball = __ballot_sync(0xffffffffu, nz);
        int wpre = __popc(ball & ((1u << lane) - 1u));
        if (lane == 0) warp_cnt[w] = __popc(ball);
        __syncthreads();
        int off = 0;
#pragma unroll
        for (int ww = 0; ww < 8; ++ww) if (ww < w) off += warp_cnt[ww];
        int total = 0;
#pragma unroll
        for (int ww = 0; ww < 8; ++ww) total += warp_cnt[ww];
        int pos = s_base + off + wpre;
        if (nz && pos < cE) { g_idx[m * cE + pos] = i; g_val[m * cE + pos] = v; }
        __syncthreads();
        if (tid == 0) s_base += total;
        __syncthreads();
    }
    int cnt = min(s_base, cE);
    if (tid == 0) g_cnt[m] = cnt;
    for (int s = cnt + tid; s < cE; s += 256) { g_idx[m * cE + s] = 0; g_val[m * cE + s] = 0.f; }
}

// ---------------- 2. Fourier features: feat[slot][33] ----------------
__global__ void k_feat(const float* __restrict__ fourierB) {
    long long slot = (long long)blockIdx.x * blockDim.x + threadIdx.x;
    if (slot >= cSLOTS) return;
    int idx = g_idx[slot];
    float val = g_val[slot];
    float row = (float)(idx / cN), col = (float)(idx % cN);
    float* f = g_feat + slot * cFEAT;
    f[0] = val;
#pragma unroll
    for (int k = 0; k < cNF; k++) {
        float t = row * fourierB[2 * k] + col * fourierB[2 * k + 1];
        // sin(2*pi*t) / cos(2*pi*t), robust to fast-math
        f[1 + k]       = sinpif(2.f * t);
        f[1 + cNF + k] = cospif(2.f * t);
    }
}

// ---------------- generic fp32 GEMM: C[M,N] = act(A[M,K] @ B[N,K]^T + bias[N]) ----------------
// 64x64 tile, BK=32, 256 threads, 4x4 per thread. Batched via blockIdx.z with strides.
template <bool SWISH>
__global__ void k_gemm(const float* __restrict__ A, const float* __restrict__ Bw,
                       const float* __restrict__ bias, float* __restrict__ C,
                       int M, int Nn, int K,
                       long long sA, long long sB, long long sBias, long long sC) {
    int z = blockIdx.z;
    A  += (long long)z * sA;
    Bw += (long long)z * sB;
    C  += (long long)z * sC;
    if (bias) bias += (long long)z * sBias;

    __shared__ float As[64][33];
    __shared__ float Bs[64][33];
    int tid = threadIdx.x;
    int tx = tid & 15, ty = tid >> 4;
    int lc = tid & 31, lr = tid >> 5;        // load: col 0..31, row base 0..7
    int m0 = blockIdx.y * 64, n0 = blockIdx.x * 64;

    float acc[4][4] = {};
    for (int k0 = 0; k0 < K; k0 += 32) {
        int gk = k0 + lc;
        bool kok = (gk < K);
#pragma unroll
        for (int i = 0; i < 8; i++) {
            int r = lr + i * 8;
            int gm = m0 + r, gn = n0 + r;
            As[r][lc] = (kok && gm < M)  ? A [(long long)gm * K + gk] : 0.f;
            Bs[r][lc] = (kok && gn < Nn) ? Bw[(long long)gn * K + gk] : 0.f;
        }
        __syncthreads();
#pragma unroll
        for (int k = 0; k < 32; k++) {
            float a[4], b[4];
#pragma unroll
            for (int i = 0; i < 4; i++) a[i] = As[ty * 4 + i][k];
#pragma unroll
            for (int j = 0; j < 4; j++) b[j] = Bs[tx * 4 + j][k];
#pragma unroll
            for (int i = 0; i < 4; i++)
#pragma unroll
                for (int j = 0; j < 4; j++) acc[i][j] += a[i] * b[j];
        }
        __syncthreads();
    }
#pragma unroll
    for (int i = 0; i < 4; i++) {
        int gm = m0 + ty * 4 + i;
        if (gm >= M) continue;
#pragma unroll
        for (int j = 0; j < 4; j++) {
            int gn = n0 + tx * 4 + j;
            if (gn >= Nn) continue;
            float v = acc[i][j] + (bias ? bias[gn] : 0.f);
            if (SWISH) v = swishf(v);
            C[(long long)gm * Nn + gn] = v;
        }
    }
}

// ---------------- 3. replace invalid entry embeddings with pad_token ----------------
__global__ void k_padfix(const float* __restrict__ pad_token) {
    int slot = blockIdx.x;
    int ba = slot / cE, s = slot % cE;
    if (s < g_cnt[ba]) return;
    g_e[(long long)slot * cHID + threadIdx.x] = pad_token[threadIdx.x];
}

// ---------------- 4. attention: scores + softmax + alpha@V + swish ----------------
// one block per (n,b,a); 256 threads.
__global__ void k_attn(const float* __restrict__ conn) {
    int gid = blockIdx.x;
    int a = gid % cA;
    int nb = gid / cA;
    int b = nb % cB, n = nb / cB;
    long long base = (((long long)n * cB + b) * cA) * cHID;
    const float* Qr = g_Qb + base + (long long)a * cHID;
    const float* Kb = g_Kb + base;
    const float* Vb = g_Vb + base;

    __shared__ float sQ[cHID];
    __shared__ float sAl[cA];
    __shared__ float sred[8];
    __shared__ float sstat;

    int tid = threadIdx.x, lane = tid & 31, w = tid >> 5;
    sQ[tid] = Qr[tid];
    __syncthreads();

    float mval = -1e30f;
    for (int c = tid; c < cA; c += 256) {
        const float* Kr = Kb + (long long)c * cHID;
        float s = 0.f;
#pragma unroll 8
        for (int i = 0; i < cHID; i++) s += sQ[i] * Kr[i];
        s = s * 0.0625f + conn[a * cA + c];   // /sqrt(256) + connectivity
        sAl[c] = s;
        mval = fmaxf(mval, s);
    }
    mval = warpMax(mval);
    if (lane == 0) sred[w] = mval;
    __syncthreads();
    if (tid == 0) {
        float mm = -1e30f;
#pragma unroll
        for (int i = 0; i < 8; i++) mm = fmaxf(mm, sred[i]);
        sstat = mm;
    }
    __syncthreads();
    float gmax = sstat;
    float psum = 0.f;
    for (int c = tid; c < cA; c += 256) {
        float ev = expf(sAl[c] - gmax);
        sAl[c] = ev;
        psum += ev;
    }
    psum = warpSum(psum);
    __syncthreads();                 // protect sred reuse + sAl writes
    if (lane == 0) sred[w] = psum;
    __syncthreads();
    if (tid == 0) {
        float tot = 0.f;
#pragma unroll
        for (int i = 0; i < 8; i++) tot += sred[i];
        sstat = tot;
    }
    __syncthreads();
    float inv = 1.f / sstat;

    float acc = 0.f;
#pragma unroll 4
    for (int c = 0; c < cA; c++) acc += sAl[c] * Vb[(long long)c * cHID + tid];
    acc *= inv;
    g_Hs[base + (long long)a * cHID + tid] = swishf(acc);   // store swish(Hm)
}

// ---------------- 5. layernorm per head + mean over heads -> h ----------------
__global__ void k_ln(const float* __restrict__ lnG, const float* __restrict__ lnB) {
    int m = blockIdx.x;
    int tid = threadIdx.x, lane = tid & 31, w = tid >> 5;
    __shared__ float sred[8];
    __shared__ float sval;
    float hacc = 0.f;
    for (int n = 0; n < cNH; n++) {
        float t = g_t2[((long long)n * cBA + m) * cHID + tid];
        float s = warpSum(t);
        if (lane == 0) sred[w] = s;
        __syncthreads();                                  // (A)
        if (tid == 0) {
            float tot = 0.f;
#pragma unroll
            for (int i = 0; i < 8; i++) tot += sred[i];
            sval = tot * (1.f / cHID);
        }
        __syncthreads();                                  // (B)
        float mean = sval;
        float d = t - mean;
        float s2 = warpSum(d * d);
        __syncthreads();                                  // before sred reuse
        if (lane == 0) sred[w] = s2;
        __syncthreads();                                  // (D)
        if (tid == 0) {
            float tot = 0.f;
#pragma unroll
            for (int i = 0; i < 8; i++) tot += sred[i];
            sval = rsqrtf(tot * (1.f / cHID) + 1e-5f);
        }
        __syncthreads();                                  // (E)
        hacc += d * sval * lnG[n * cHID + tid] + lnB[n * cHID + tid];
        __syncthreads();                                  // before next head's sval/sred writes
    }
    g_h[(long long)m * cHID + tid] = hacc * 0.25f;
}

// ---------------- host-side launch helpers ----------------
static void gemm(const float* A, const float* B, const float* bias, float* C,
                 int M, int N, int K, bool swish,
                 long long sA = 0, long long sB = 0, long long sBias = 0, long long sC = 0,
                 int batch = 1) {
    dim3 grid((N + 63) / 64, (M + 63) / 64, batch);
    if (swish) k_gemm<true ><<<grid, 256>>>(A, B, bias, C, M, N, K, sA, sB, sBias, sC);
    else       k_gemm<false><<<grid, 256>>>(A, B, bias, C, M, N, K, sA, sB, sBias, sC);
}

extern "C" void kernel_launch(void* const* d_in, const int* in_sizes, int n_in,
                              void* d_out, int out_size) {
    const float* x       = (const float*)d_in[0];
    const float* fourier = (const float*)d_in[1];
    const float* encW1   = (const float*)d_in[2];
    const float* encB1   = (const float*)d_in[3];
    const float* encW2   = (const float*)d_in[4];
    const float* encB2   = (const float*)d_in[5];
    const float* padTok  = (const float*)d_in[6];
    const float* compW1  = (const float*)d_in[7];
    const float* compB1  = (const float*)d_in[8];
    const float* compW2  = (const float*)d_in[9];
    const float* compB2  = (const float*)d_in[10];
    const float* conn    = (const float*)d_in[11];
    const float* qW      = (const float*)d_in[12];
    const float* kW      = (const float*)d_in[13];
    const float* vW      = (const float*)d_in[14];
    const float* fpW1    = (const float*)d_in[15];
    const float* fpB1    = (const float*)d_in[16];
    const float* fpW2    = (const float*)d_in[17];
    const float* fpB2    = (const float*)d_in[18];
    const float* lnG     = (const float*)d_in[19];
    const float* lnB     = (const float*)d_in[20];
    const float* outW    = (const float*)d_in[21];
    const float* outB    = (const float*)d_in[22];
    float* out = (float*)d_out;

    float *pFeat, *pH1, *pE, *pC1, *pH, *pQ, *pK, *pV, *pHs, *pT1, *pT2;
    cudaGetSymbolAddress((void**)&pFeat, g_feat);
    cudaGetSymbolAddress((void**)&pH1,   g_H1);
    cudaGetSymbolAddress((void**)&pE,    g_e);
    cudaGetSymbolAddress((void**)&pC1,   g_c1);
    cudaGetSymbolAddress((void**)&pH,    g_h);
    cudaGetSymbolAddress((void**)&pQ,    g_Qb);
    cudaGetSymbolAddress((void**)&pK,    g_Kb);
    cudaGetSymbolAddress((void**)&pV,    g_Vb);
    cudaGetSymbolAddress((void**)&pHs,   g_Hs);
    cudaGetSymbolAddress((void**)&pT1,   g_t1);
    cudaGetSymbolAddress((void**)&pT2,   g_t2);

    // entry gather + features
    k_gather<<<cBA, 256>>>(x);
    k_feat<<<(cSLOTS + 255) / 256, 256>>>(fourier);

    // entry encoder MLP
    gemm(pFeat, encW1, encB1, pH1, cSLOTS, cHID, cFEAT, true);
    gemm(pH1,   encW2, encB2, pE,  cSLOTS, cHID, cHID,  false);
    k_padfix<<<cSLOTS, 256>>>(padTok);

    // per-agent compression
    gemm(pE,  compW1, compB1, pC1, cBA, 2 * cHID, cE * cHID, true);
    gemm(pC1, compW2, compB2, pH,  cBA, cHID,     2 * cHID,  false);

    // message passing
    const long long sW = (long long)cHID * cHID;
    const long long sM = (long long)cBA * cHID;
    for (int s = 0; s < cSTEPS; s++) {
        gemm(pH, qW, nullptr, pQ, cBA, cHID, cHID, false, 0, sW, 0, sM, cNH);
        gemm(pH, kW, nullptr, pK, cBA, cHID, cHID, false, 0, sW, 0, sM, cNH);
        gemm(pH, vW, nullptr, pV, cBA, cHID, cHID, false, 0, sW, 0, sM, cNH);
        k_attn<<<cNH * cBA, 256>>>(conn);
        gemm(pHs, fpW1, fpB1, pT1, cBA, cHID, cHID, true,  sM, sW, cHID, sM, cNH);
        gemm(pT1, fpW2, fpB2, pT2, cBA, cHID, cHID, false, sM, sW, cHID, sM, cNH);
        k_ln<<<cBA, 256>>>(lnG, lnB);
    }

    // output projection
    gemm(pH, outW, outB, out, cBA, cOUT, cHID, false);
}

// round 8
// speedup vs baseline: 1.3207x; 1.3207x over previous
#include <cuda_runtime.h>
#include <math.h>

// ---------------- problem constants ----------------
#define cB    32
#define cA    100
#define cD    10000
#define cHID  256
#define cNH   4
#define cOUT  10000
#define cNF   16
#define cE    100
#define cN    100
#define cFEAT 33          // 1 + 2*NFREQ
#define cBA   (cB*cA)     // 3200
#define cSLOTS (cBA*cE)   // 320000
#define cSTEPS 3

// ---------------- scratch (device globals; no allocs allowed) ----------------
__device__ int   g_cnt[cBA];
__device__ int   g_idx[cSLOTS];
__device__ float g_val[cSLOTS];
__device__ float g_feat[(long long)cSLOTS*cFEAT];
__device__ float g_H1 [(long long)cSLOTS*cHID];
__device__ float g_e  [(long long)cSLOTS*cHID];
__device__ float g_c1 [cBA*2*cHID];
__device__ float g_h  [cBA*cHID];
__device__ float g_Qb [cNH*cBA*cHID];
__device__ float g_Kb [cNH*cBA*cHID];
__device__ float g_Vb [cNH*cBA*cHID];
__device__ float g_Hs [cNH*cBA*cHID];   // swish(Hm)
__device__ float g_t1 [cNH*cBA*cHID];
__device__ float g_t2 [cNH*cBA*cHID];

// ---------------- helpers ----------------
__device__ __forceinline__ float swishf(float v) { return v / (1.f + expf(-v)); }

__device__ __forceinline__ float warpSum(float v) {
#pragma unroll
    for (int o = 16; o > 0; o >>= 1) v += __shfl_xor_sync(0xffffffffu, v, o);
    return v;
}
__device__ __forceinline__ float warpMax(float v) {
#pragma unroll
    for (int o = 16; o > 0; o >>= 1) v = fmaxf(v, __shfl_xor_sync(0xffffffffu, v, o));
    return v;
}

// round fp32 -> tf32 (round to nearest, unbiased) keeping fp32 bit container
__device__ __forceinline__ float tf32r(float x) {
    unsigned r;
    asm("cvt.rna.tf32.f32 %0, %1;" : "=r"(r) : "f"(x));
    return __uint_as_float(r);
}

// one m16n8k8 tf32 mma, fp32 accumulate
__device__ __forceinline__ void mma8(float* c, const unsigned* a, const unsigned* b) {
    asm volatile(
        "mma.sync.aligned.m16n8k8.row.col.f32.tf32.tf32.f32 "
        "{%0,%1,%2,%3}, {%4,%5,%6,%7}, {%8,%9}, {%0,%1,%2,%3};"
        : "+f"(c[0]), "+f"(c[1]), "+f"(c[2]), "+f"(c[3])
        : "r"(a[0]), "r"(a[1]), "r"(a[2]), "r"(a[3]), "r"(b[0]), "r"(b[1]));
}

// ---------------- 1. ragged gather of nonzeros (stable, ascending) ----------------
__global__ void k_gather(const float* __restrict__ x) {
    int m = blockIdx.x;
    const float* xr = x + (long long)m * cD;
    int tid = threadIdx.x, lane = tid & 31, w = tid >> 5;
    __shared__ int warp_cnt[8];
    __shared__ int s_base;
    if (tid == 0) s_base = 0;
    __syncthreads();
    for (int c0 = 0; c0 < cD; c0 += 256) {
        int i = c0 + tid;
        float v = (i < cD) ? xr[i] : 0.f;
        bool nz = (i < cD) && (v != 0.f);
        unsigned ball = __ballot_sync(0xffffffffu, nz);
        int wpre = __popc(ball & ((1u << lane) - 1u));
        if (lane == 0) warp_cnt[w] = __popc(ball);
        __syncthreads();
        int off = 0;
#pragma unroll
        for (int ww = 0; ww < 8; ++ww) if (ww < w) off += warp_cnt[ww];
        int total = 0;
#pragma unroll
        for (int ww = 0; ww < 8; ++ww) total += warp_cnt[ww];
        int pos = s_base + off + wpre;
        if (nz && pos < cE) { g_idx[m * cE + pos] = i; g_val[m * cE + pos] = v; }
        __syncthreads();
        if (tid == 0) s_base += total;
        __syncthreads();
    }
    int cnt = min(s_base, cE);
    if (tid == 0) g_cnt[m] = cnt;
    for (int s = cnt + tid; s < cE; s += 256) { g_idx[m * cE + s] = 0; g_val[m * cE + s] = 0.f; }
}

// ---------------- 2. Fourier features: feat[slot][33] ----------------
__global__ void k_feat(const float* __restrict__ fourierB) {
    long long slot = (long long)blockIdx.x * blockDim.x + threadIdx.x;
    if (slot >= cSLOTS) return;
    int idx = g_idx[slot];
    float val = g_val[slot];
    float row = (float)(idx / cN), col = (float)(idx % cN);
    float* f = g_feat + slot * cFEAT;
    f[0] = val;
#pragma unroll
    for (int k = 0; k < cNF; k++) {
        float t = row * fourierB[2 * k] + col * fourierB[2 * k + 1];
        f[1 + k]       = sinpif(2.f * t);
        f[1 + cNF + k] = cospif(2.f * t);
    }
}

// ---------------- tensor-core tf32 GEMM: C = act(A[M,K] @ B[N,K]^T + bias) ----------------
// TMxTN block tile, BK=16, WMxWN warps each computing (TM/WM)x(TN/WN) via m16n8k8.
// Batched via blockIdx.z with element strides. Smem stride 20 -> conflict-free frag LDS.
// float4 global loads ONLY when K % 4 == 0 (row starts then stay 16B-aligned);
// otherwise guarded scalar loads (the K=33 feature GEMM). This is the R4
// misaligned-address fix.
template <int TM, int TN, int WM, int WN, bool SWISH>
__global__ void __launch_bounds__(WM * WN * 32)
k_tgemm(const float* __restrict__ A, const float* __restrict__ Bw,
        const float* __restrict__ bias, float* __restrict__ C,
        int M, int Nn, int K,
        long long sA_, long long sB_, long long sBias, long long sC) {
    constexpr int THREADS = WM * WN * 32;
    constexpr int MT = TM / WM / 16;   // m16 tiles per warp
    constexpr int NT = TN / WN / 8;    // n8  tiles per warp
    constexpr int SS = 20;             // smem row stride (floats)

    __shared__ float shA[2][TM * SS];
    __shared__ float shB[2][TN * SS];

    int z = blockIdx.z;
    A  += (long long)z * sA_;
    Bw += (long long)z * sB_;
    C  += (long long)z * sC;
    const float* bptr = bias ? bias + (long long)z * sBias : nullptr;

    int tid = threadIdx.x;
    int m0 = blockIdx.y * TM, n0 = blockIdx.x * TN;
    int wid = tid >> 5, lane = tid & 31;
    int wm = wid / WN, wn = wid % WN;
    int g = lane >> 2, tg = lane & 3;

    const bool vec4 = ((K & 3) == 0);   // uniform across block

    float acc[MT][NT][4];
#pragma unroll
    for (int mt = 0; mt < MT; mt++)
#pragma unroll
        for (int nt = 0; nt < NT; nt++)
#pragma unroll
            for (int i = 0; i < 4; i++) acc[mt][nt][i] = 0.f;

    int nK = (K + 15) / 16;

    auto load = [&](int k0, int b) {
        // A tile: TM rows x 16 cols, one quad (4 floats) per iteration slot
        for (int qi = tid; qi < TM * 4; qi += THREADS) {
            int r = qi >> 2, q = (qi & 3) * 4;
            int gm = m0 + r, gk = k0 + q;
            float4 v = make_float4(0.f, 0.f, 0.f, 0.f);
            if (gm < M) {
                const float* src = A + (long long)gm * K + gk;
                if (vec4 && gk + 3 < K) v = *(const float4*)src;
                else {
                    if (gk     < K) v.x = src[0];
                    if (gk + 1 < K) v.y = src[1];
                    if (gk + 2 < K) v.z = src[2];
                    if (gk + 3 < K) v.w = src[3];
                }
            }
            float4 w = make_float4(tf32r(v.x), tf32r(v.y), tf32r(v.z), tf32r(v.w));
            *(float4*)(&shA[b][r * SS + q]) = w;
        }
        // B tile: TN rows (n) x 16 cols (k)
        for (int qi = tid; qi < TN * 4; qi += THREADS) {
            int r = qi >> 2, q = (qi & 3) * 4;
            int gn = n0 + r, gk = k0 + q;
            float4 v = make_float4(0.f, 0.f, 0.f, 0.f);
            if (gn < Nn) {
                const float* src = Bw + (long long)gn * K + gk;
                if (vec4 && gk + 3 < K) v = *(const float4*)src;
                else {
                    if (gk     < K) v.x = src[0];
                    if (gk + 1 < K) v.y = src[1];
                    if (gk + 2 < K) v.z = src[2];
                    if (gk + 3 < K) v.w = src[3];
                }
            }
            float4 w = make_float4(tf32r(v.x), tf32r(v.y), tf32r(v.z), tf32r(v.w));
            *(float4*)(&shB[b][r * SS + q]) = w;
        }
    };

    auto compute = [&](int b) {
        const float* sa = shA[b];
        const float* sb = shB[b];
#pragma unroll
        for (int kk = 0; kk < 16; kk += 8) {
            unsigned af[MT][4], bf[NT][2];
#pragma unroll
            for (int mt = 0; mt < MT; mt++) {
                int row = wm * (MT * 16) + mt * 16;
                af[mt][0] = __float_as_uint(sa[(row + g    ) * SS + kk + tg    ]);
                af[mt][1] = __float_as_uint(sa[(row + g + 8) * SS + kk + tg    ]);
                af[mt][2] = __float_as_uint(sa[(row + g    ) * SS + kk + tg + 4]);
                af[mt][3] = __float_as_uint(sa[(row + g + 8) * SS + kk + tg + 4]);
            }
#pragma unroll
            for (int nt = 0; nt < NT; nt++) {
                int col = wn * (NT * 8) + nt * 8 + g;
                bf[nt][0] = __float_as_uint(sb[col * SS + kk + tg    ]);
                bf[nt][1] = __float_as_uint(sb[col * SS + kk + tg + 4]);
            }
#pragma unroll
            for (int mt = 0; mt < MT; mt++)
#pragma unroll
                for (int nt = 0; nt < NT; nt++) mma8(acc[mt][nt], af[mt], bf[nt]);
        }
    };

    load(0, 0);
    __syncthreads();
    int buf = 0;
    for (int it = 0; it < nK; it++) {
        if (it + 1 < nK) load((it + 1) * 16, buf ^ 1);
        compute(buf);
        __syncthreads();
        buf ^= 1;
    }

    // epilogue
#pragma unroll
    for (int mt = 0; mt < MT; mt++) {
        int r0 = m0 + wm * (MT * 16) + mt * 16;
#pragma unroll
        for (int nt = 0; nt < NT; nt++) {
            int c0 = n0 + wn * (NT * 8) + nt * 8 + 2 * tg;
#pragma unroll
            for (int i = 0; i < 4; i++) {
                int gm = r0 + g + (i >> 1) * 8;
                int gn = c0 + (i & 1);
                if (gm < M && gn < Nn) {
                    float v = acc[mt][nt][i] + (bptr ? bptr[gn] : 0.f);
                    if (SWISH) v = swishf(v);
                    C[(long long)gm * Nn + gn] = v;
                }
            }
        }
    }
}

// ---------------- 3. replace invalid entry embeddings with pad_token ----------------
__global__ void k_padfix(const float* __restrict__ pad_token) {
    int ba = blockIdx.x;
    int cnt = g_cnt[ba];
    float pv = pad_token[threadIdx.x];
    for (int s = cnt; s < cE; s++)
        g_e[((long long)ba * cE + s) * cHID + threadIdx.x] = pv;
}

// ---------------- 4. attention: scores + softmax + alpha@V + swish ----------------
__global__ void k_attn(const float* __restrict__ conn) {
    int gid = blockIdx.x;
    int a = gid % cA;
    int nb = gid / cA;
    int b = nb % cB, n = nb / cB;
    long long base = (((long long)n * cB + b) * cA) * cHID;
    const float* Qr = g_Qb + base + (long long)a * cHID;
    const float* Kb = g_Kb + base;
    const float* Vb = g_Vb + base;

    __shared__ float sQ[cHID];
    __shared__ float sAl[cA];
    __shared__ float sred[8];
    __shared__ float sstat;

    int tid = threadIdx.x, lane = tid & 31, w = tid >> 5;
    sQ[tid] = Qr[tid];
    __syncthreads();

    float mval = -1e30f;
    for (int c = tid; c < cA; c += 256) {
        const float* Kr = Kb + (long long)c * cHID;
        float s = 0.f;
#pragma unroll 8
        for (int i = 0; i < cHID; i++) s += sQ[i] * Kr[i];
        s = s * 0.0625f + conn[a * cA + c];
        sAl[c] = s;
        mval = fmaxf(mval, s);
    }
    mval = warpMax(mval);
    if (lane == 0) sred[w] = mval;
    __syncthreads();
    if (tid == 0) {
        float mm = -1e30f;
#pragma unroll
        for (int i = 0; i < 8; i++) mm = fmaxf(mm, sred[i]);
        sstat = mm;
    }
    __syncthreads();
    float gmax = sstat;
    float psum = 0.f;
    for (int c = tid; c < cA; c += 256) {
        float ev = expf(sAl[c] - gmax);
        sAl[c] = ev;
        psum += ev;
    }
    psum = warpSum(psum);
    __syncthreads();
    if (lane == 0) sred[w] = psum;
    __syncthreads();
    if (tid == 0) {
        float tot = 0.f;
#pragma unroll
        for (int i = 0; i < 8; i++) tot += sred[i];
        sstat = tot;
    }
    __syncthreads();
    float inv = 1.f / sstat;

    float acc = 0.f;
#pragma unroll 4
    for (int c = 0; c < cA; c++) acc += sAl[c] * Vb[(long long)c * cHID + tid];
    acc *= inv;
    g_Hs[base + (long long)a * cHID + tid] = swishf(acc);
}

// ---------------- 5. layernorm per head + mean over heads -> h ----------------
__global__ void k_ln(const float* __restrict__ lnG, const float* __restrict__ lnB) {
    int m = blockIdx.x;
    int tid = threadIdx.x, lane = tid & 31, w = tid >> 5;
    __shared__ float sred[8];
    __shared__ float sval;
    float hacc = 0.f;
    for (int n = 0; n < cNH; n++) {
        float t = g_t2[((long long)n * cBA + m) * cHID + tid];
        float s = warpSum(t);
        if (lane == 0) sred[w] = s;
        __syncthreads();
        if (tid == 0) {
            float tot = 0.f;
#pragma unroll
            for (int i = 0; i < 8; i++) tot += sred[i];
            sval = tot * (1.f / cHID);
        }
        __syncthreads();
        float mean = sval;
        float d = t - mean;
        float s2 = warpSum(d * d);
        __syncthreads();
        if (lane == 0) sred[w] = s2;
        __syncthreads();
        if (tid == 0) {
            float tot = 0.f;
#pragma unroll
            for (int i = 0; i < 8; i++) tot += sred[i];
            sval = rsqrtf(tot * (1.f / cHID) + 1e-5f);
        }
        __syncthreads();
        hacc += d * sval * lnG[n * cHID + tid] + lnB[n * cHID + tid];
        __syncthreads();
    }
    g_h[(long long)m * cHID + tid] = hacc * 0.25f;
}

// ---------------- host-side launch helpers ----------------
template <bool SW>
static void tg128(const float* A, const float* B, const float* bias, float* C,
                  int M, int N, int K,
                  long long sA = 0, long long sB = 0, long long sb = 0, long long sC = 0,
                  int batch = 1) {
    dim3 grid((N + 127) / 128, (M + 127) / 128, batch);
    k_tgemm<128, 128, 2, 4, SW><<<grid, 256>>>(A, B, bias, C, M, N, K, sA, sB, sb, sC);
}
template <bool SW>
static void tg64(const float* A, const float* B, const float* bias, float* C,
                 int M, int N, int K,
                 long long sA = 0, long long sB = 0, long long sb = 0, long long sC = 0,
                 int batch = 1) {
    dim3 grid((N + 63) / 64, (M + 63) / 64, batch);
    k_tgemm<64, 64, 2, 2, SW><<<grid, 128>>>(A, B, bias, C, M, N, K, sA, sB, sb, sC);
}

extern "C" void kernel_launch(void* const* d_in, const int* in_sizes, int n_in,
                              void* d_out, int out_size) {
    const float* x       = (const float*)d_in[0];
    const float* fourier = (const float*)d_in[1];
    const float* encW1   = (const float*)d_in[2];
    const float* encB1   = (const float*)d_in[3];
    const float* encW2   = (const float*)d_in[4];
    const float* encB2   = (const float*)d_in[5];
    const float* padTok  = (const float*)d_in[6];
    const float* compW1  = (const float*)d_in[7];
    const float* compB1  = (const float*)d_in[8];
    const float* compW2  = (const float*)d_in[9];
    const float* compB2  = (const float*)d_in[10];
    const float* conn    = (const float*)d_in[11];
    const float* qW      = (const float*)d_in[12];
    const float* kW      = (const float*)d_in[13];
    const float* vW      = (const float*)d_in[14];
    const float* fpW1    = (const float*)d_in[15];
    const float* fpB1    = (const float*)d_in[16];
    const float* fpW2    = (const float*)d_in[17];
    const float* fpB2    = (const float*)d_in[18];
    const float* lnG     = (const float*)d_in[19];
    const float* lnB     = (const float*)d_in[20];
    const float* outW    = (const float*)d_in[21];
    const float* outB    = (const float*)d_in[22];
    float* out = (float*)d_out;

    float *pFeat, *pH1, *pE, *pC1, *pH, *pQ, *pK, *pV, *pHs, *pT1, *pT2;
    cudaGetSymbolAddress((void**)&pFeat, g_feat);
    cudaGetSymbolAddress((void**)&pH1,   g_H1);
    cudaGetSymbolAddress((void**)&pE,    g_e);
    cudaGetSymbolAddress((void**)&pC1,   g_c1);
    cudaGetSymbolAddress((void**)&pH,    g_h);
    cudaGetSymbolAddress((void**)&pQ,    g_Qb);
    cudaGetSymbolAddress((void**)&pK,    g_Kb);
    cudaGetSymbolAddress((void**)&pV,    g_Vb);
    cudaGetSymbolAddress((void**)&pHs,   g_Hs);
    cudaGetSymbolAddress((void**)&pT1,   g_t1);
    cudaGetSymbolAddress((void**)&pT2,   g_t2);

    // entry gather + features
    k_gather<<<cBA, 256>>>(x);
    k_feat<<<(cSLOTS + 255) / 256, 256>>>(fourier);

    // entry encoder MLP (tf32 tensor cores; K=33 -> scalar-load path)
    tg128<true >(pFeat, encW1, encB1, pH1, cSLOTS, cHID, cFEAT);
    tg128<false>(pH1,   encW2, encB2, pE,  cSLOTS, cHID, cHID);
    k_padfix<<<cBA, 256>>>(padTok);

    // per-agent compression (64x64 tiles -> enough blocks for M=3200)
    tg64<true >(pE,  compW1, compB1, pC1, cBA, 2 * cHID, cE * cHID);
    tg64<false>(pC1, compW2, compB2, pH,  cBA, cHID,     2 * cHID);

    // message passing
    const long long sW = (long long)cHID * cHID;
    const long long sM = (long long)cBA * cHID;
    for (int s = 0; s < cSTEPS; s++) {
        tg128<false>(pH, qW, nullptr, pQ, cBA, cHID, cHID, 0, sW, 0, sM, cNH);
        tg128<false>(pH, kW, nullptr, pK, cBA, cHID, cHID, 0, sW, 0, sM, cNH);
        tg128<false>(pH, vW, nullptr, pV, cBA, cHID, cHID, 0, sW, 0, sM, cNH);
        k_attn<<<cNH * cBA, 256>>>(conn);
        tg128<true >(pHs, fpW1, fpB1, pT1, cBA, cHID, cHID, sM, sW, cHID, sM, cNH);
        tg128<false>(pT1, fpW2, fpB2, pT2, cBA, cHID, cHID, sM, sW, cHID, sM, cNH);
        k_ln<<<cBA, 256>>>(lnG, lnB);
    }

    // output projection
    tg128<false>(pH, outW, outB, out, cBA, cOUT, cHID);
}

// round 9
// speedup vs baseline: 2.5441x; 1.9264x over previous
#include <cuda_runtime.h>
#include <cuda_bf16.h>
#include <math.h>

// ---------------- problem constants ----------------
#define cB    32
#define cA    100
#define cD    10000
#define cHID  256
#define cNH   4
#define cOUT  10000
#define cNF   16
#define cE    100
#define cN    100
#define cFEAT 33          // 1 + 2*NFREQ
#define cBA   (cB*cA)     // 3200
#define cSLOTS (cBA*cE)   // 320000
#define cSTEPS 3
#define cKS   4           // split-K factor for comp1
#define cKCH  (cE*cHID/cKS)   // 6400

// ---------------- scratch (device globals; no allocs allowed) ----------------
__device__ int   g_cnt[cBA];
__device__ int   g_idx[cSLOTS];
__device__ float g_val[cSLOTS];
__device__ float g_feat[(long long)cSLOTS*cFEAT];
__device__ float g_H1 [(long long)cSLOTS*cHID];
__device__ float g_e  [(long long)cSLOTS*cHID];
__device__ float g_ck [cKS*cBA*2*cHID];   // split-K partials for comp1
__device__ float g_c1 [cBA*2*cHID];
__device__ float g_h  [cBA*cHID];
__device__ float g_Qb [cNH*cBA*cHID];
__device__ float g_Kb [cNH*cBA*cHID];
__device__ float g_Vb [cNH*cBA*cHID];
__device__ float g_Hs [cNH*cBA*cHID];   // swish(Hm)
__device__ float g_t1 [cNH*cBA*cHID];
__device__ float g_t2 [cNH*cBA*cHID];

// ---------------- helpers ----------------
__device__ __forceinline__ float swishf(float v) { return v / (1.f + expf(-v)); }

__device__ __forceinline__ float warpSum(float v) {
#pragma unroll
    for (int o = 16; o > 0; o >>= 1) v += __shfl_xor_sync(0xffffffffu, v, o);
    return v;
}
__device__ __forceinline__ float warpMax(float v) {
#pragma unroll
    for (int o = 16; o > 0; o >>= 1) v = fmaxf(v, __shfl_xor_sync(0xffffffffu, v, o));
    return v;
}

// pack two floats -> (hi bf16 pair word, lo bf16 pair word); low 16 bits = lower k
__device__ __forceinline__ void pack2(float x0, float x1, unsigned& hi, unsigned& lo) {
    __nv_bfloat16 h0 = __float2bfloat16_rn(x0);
    __nv_bfloat16 h1 = __float2bfloat16_rn(x1);
    float r0 = x0 - __bfloat162float(h0);
    float r1 = x1 - __bfloat162float(h1);
    __nv_bfloat16 l0 = __float2bfloat16_rn(r0);
    __nv_bfloat16 l1 = __float2bfloat16_rn(r1);
    hi = ((unsigned)__bfloat16_as_ushort(h1) << 16) | (unsigned)__bfloat16_as_ushort(h0);
    lo = ((unsigned)__bfloat16_as_ushort(l1) << 16) | (unsigned)__bfloat16_as_ushort(l0);
}

// one m16n8k16 bf16 mma, fp32 accumulate
__device__ __forceinline__ void mma16(float* c, const unsigned* a, const unsigned* b) {
    asm volatile(
        "mma.sync.aligned.m16n8k16.row.col.f32.bf16.bf16.f32 "
        "{%0,%1,%2,%3}, {%4,%5,%6,%7}, {%8,%9}, {%0,%1,%2,%3};"
        : "+f"(c[0]), "+f"(c[1]), "+f"(c[2]), "+f"(c[3])
        : "r"(a[0]), "r"(a[1]), "r"(a[2]), "r"(a[3]), "r"(b[0]), "r"(b[1]));
}

// ---------------- 1. ragged gather of nonzeros (stable, ascending) ----------------
__global__ void k_gather(const float* __restrict__ x) {
    int m = blockIdx.x;
    const float* xr = x + (long long)m * cD;
    int tid = threadIdx.x, lane = tid & 31, w = tid >> 5;
    __shared__ int warp_cnt[8];
    __shared__ int s_base;
    if (tid == 0) s_base = 0;
    __syncthreads();
    for (int c0 = 0; c0 < cD; c0 += 256) {
        int i = c0 + tid;
        float v = (i < cD) ? xr[i] : 0.f;
        bool nz = (i < cD) && (v != 0.f);
        unsigned ball = __ballot_sync(0xffffffffu, nz);
        int wpre = __popc(ball & ((1u << lane) - 1u));
        if (lane == 0) warp_cnt[w] = __popc(ball);
        __syncthreads();
        int off = 0;
#pragma unroll
        for (int ww = 0; ww < 8; ++ww) if (ww < w) off += warp_cnt[ww];
        int total = 0;
#pragma unroll
        for (int ww = 0; ww < 8; ++ww) total += warp_cnt[ww];
        int pos = s_base + off + wpre;
        if (nz && pos < cE) { g_idx[m * cE + pos] = i; g_val[m * cE + pos] = v; }
        __syncthreads();
        if (tid == 0) s_base += total;
        __syncthreads();
    }
    int cnt = min(s_base, cE);
    if (tid == 0) g_cnt[m] = cnt;
    for (int s = cnt + tid; s < cE; s += 256) { g_idx[m * cE + s] = 0; g_val[m * cE + s] = 0.f; }
}

// ---------------- 2. Fourier features: feat[slot][33] ----------------
__global__ void k_feat(const float* __restrict__ fourierB) {
    long long slot = (long long)blockIdx.x * blockDim.x + threadIdx.x;
    if (slot >= cSLOTS) return;
    int idx = g_idx[slot];
    float val = g_val[slot];
    float row = (float)(idx / cN), col = (float)(idx % cN);
    float* f = g_feat + slot * cFEAT;
    f[0] = val;
#pragma unroll
    for (int k = 0; k < cNF; k++) {
        float t = row * fourierB[2 * k] + col * fourierB[2 * k + 1];
        f[1 + k]       = sinpif(2.f * t);
        f[1 + cNF + k] = cospif(2.f * t);
    }
}

// ---------------- bf16x2 tensor-core GEMM: C = act(A[M,K] @ B[N,K]^T + bias) ----------------
// A,B fp32 in gmem, split on the fly into hi/lo bf16 (3-mma scheme -> ~fp32 accuracy).
// BK=16 per stage, double buffered. Smem word layout: row r has 20 uint32 words;
// words 0..7 = hi bf16 pairs (k=2j,2j+1), words 8..15 = lo pairs, 16..19 pad.
// Stride 20 words -> all 32 lanes hit distinct banks on fragment loads.
// lda/ldb are row strides (elements), allowing split-K slicing of big-K GEMMs.
template <int TM, int TN, int WM, int WN, bool SWISH>
__global__ void __launch_bounds__(WM * WN * 32, (WM * WN * 32 >= 256) ? 2 : 4)
k_tgemm(const float* __restrict__ A, const float* __restrict__ Bw,
        const float* __restrict__ bias, float* __restrict__ C,
        int M, int Nn, int K, int lda, int ldb,
        long long sA_, long long sB_, long long sBias, long long sC) {
    constexpr int THREADS = WM * WN * 32;
    constexpr int MT = TM / WM / 16;   // m16 tiles per warp
    constexpr int NT = TN / WN / 8;    // n8  tiles per warp
    constexpr int WS = 20;             // words per smem row

    __shared__ unsigned shA[2][TM * WS];
    __shared__ unsigned shB[2][TN * WS];

    int z = blockIdx.z;
    A  += (long long)z * sA_;
    Bw += (long long)z * sB_;
    C  += (long long)z * sC;
    const float* bptr = bias ? bias + (long long)z * sBias : nullptr;

    int tid = threadIdx.x;
    int m0 = blockIdx.y * TM, n0 = blockIdx.x * TN;
    int wid = tid >> 5, lane = tid & 31;
    int wm = wid / WN, wn = wid % WN;
    int g = lane >> 2, tg = lane & 3;

    const bool vec4 = ((lda & 3) == 0) && ((ldb & 3) == 0) && ((K & 3) == 0);

    float acc[MT][NT][4];
#pragma unroll
    for (int mt = 0; mt < MT; mt++)
#pragma unroll
        for (int nt = 0; nt < NT; nt++)
#pragma unroll
            for (int i = 0; i < 4; i++) acc[mt][nt][i] = 0.f;

    int nK = (K + 15) / 16;

    auto load = [&](int k0, int b) {
#pragma unroll 2
        for (int qi = tid; qi < TM * 4; qi += THREADS) {
            int r = qi >> 2, q = qi & 3;        // q: which 4-float group in k16
            int gm = m0 + r, gk = k0 + q * 4;
            float4 v = make_float4(0.f, 0.f, 0.f, 0.f);
            if (gm < M) {
                const float* src = A + (long long)gm * lda + gk;
                if (vec4 && gk + 3 < K) v = *(const float4*)src;
                else {
                    if (gk     < K) v.x = src[0];
                    if (gk + 1 < K) v.y = src[1];
                    if (gk + 2 < K) v.z = src[2];
                    if (gk + 3 < K) v.w = src[3];
                }
            }
            unsigned h0, l0, h1, l1;
            pack2(v.x, v.y, h0, l0);
            pack2(v.z, v.w, h1, l1);
            unsigned* dst = &shA[b][r * WS];
            dst[2 * q]     = h0; dst[2 * q + 1]     = h1;
            dst[8 + 2 * q] = l0; dst[8 + 2 * q + 1] = l1;
        }
#pragma unroll 2
        for (int qi = tid; qi < TN * 4; qi += THREADS) {
            int r = qi >> 2, q = qi & 3;
            int gn = n0 + r, gk = k0 + q * 4;
            float4 v = make_float4(0.f, 0.f, 0.f, 0.f);
            if (gn < Nn) {
                const float* src = Bw + (long long)gn * ldb + gk;
                if (vec4 && gk + 3 < K) v = *(const float4*)src;
                else {
                    if (gk     < K) v.x = src[0];
                    if (gk + 1 < K) v.y = src[1];
                    if (gk + 2 < K) v.z = src[2];
                    if (gk + 3 < K) v.w = src[3];
                }
            }
            unsigned h0, l0, h1, l1;
            pack2(v.x, v.y, h0, l0);
            pack2(v.z, v.w, h1, l1);
            unsigned* dst = &shB[b][r * WS];
            dst[2 * q]     = h0; dst[2 * q + 1]     = h1;
            dst[8 + 2 * q] = l0; dst[8 + 2 * q + 1] = l1;
        }
    };

    auto compute = [&](int b) {
        const unsigned* sa = shA[b];
        const unsigned* sb = shB[b];
        unsigned bhi[NT][2], blo[NT][2];
#pragma unroll
        for (int nt = 0; nt < NT; nt++) {
            int col = (wn * NT + nt) * 8 + g;
            const unsigned* p = sb + col * WS;
            bhi[nt][0] = p[tg];     bhi[nt][1] = p[tg + 4];
            blo[nt][0] = p[tg + 8]; blo[nt][1] = p[tg + 12];
        }
#pragma unroll
        for (int mt = 0; mt < MT; mt++) {
            int row = (wm * MT + mt) * 16;
            const unsigned* p0 = sa + (row + g) * WS;
            const unsigned* p1 = sa + (row + g + 8) * WS;
            unsigned ahi[4], alo[4];
            ahi[0] = p0[tg];     ahi[1] = p1[tg];     ahi[2] = p0[tg + 4];  ahi[3] = p1[tg + 4];
            alo[0] = p0[tg + 8]; alo[1] = p1[tg + 8]; alo[2] = p0[tg + 12]; alo[3] = p1[tg + 12];
#pragma unroll
            for (int nt = 0; nt < NT; nt++) {
                mma16(acc[mt][nt], ahi, bhi[nt]);
                mma16(acc[mt][nt], ahi, blo[nt]);
                mma16(acc[mt][nt], alo, bhi[nt]);
            }
        }
    };

    load(0, 0);
    __syncthreads();
    int buf = 0;
    for (int it = 0; it < nK; it++) {
        if (it + 1 < nK) load((it + 1) * 16, buf ^ 1);
        compute(buf);
        __syncthreads();
        buf ^= 1;
    }

    // epilogue (c0:(g,2tg) c1:(g,2tg+1) c2:(g+8,2tg) c3:(g+8,2tg+1))
#pragma unroll
    for (int mt = 0; mt < MT; mt++) {
        int r0 = m0 + (wm * MT + mt) * 16;
#pragma unroll
        for (int nt = 0; nt < NT; nt++) {
            int c0 = n0 + (wn * NT + nt) * 8 + 2 * tg;
#pragma unroll
            for (int i = 0; i < 4; i++) {
                int gm = r0 + g + (i >> 1) * 8;
                int gn = c0 + (i & 1);
                if (gm < M && gn < Nn) {
                    float v = acc[mt][nt][i] + (bptr ? bptr[gn] : 0.f);
                    if (SWISH) v = swishf(v);
                    C[(long long)gm * Nn + gn] = v;
                }
            }
        }
    }
}

// ---------------- split-K reduce for comp1: swish(sum_z part + bias) ----------------
__global__ void k_red(const float* __restrict__ part, const float* __restrict__ bias,
                      float* __restrict__ out) {
    int i = blockIdx.x * 256 + threadIdx.x;
    const int MN = cBA * 2 * cHID;
    if (i >= MN) return;
    float s = part[i] + part[i + MN] + part[i + 2 * MN] + part[i + 3 * MN];
    s += bias[i % (2 * cHID)];
    out[i] = swishf(s);
}

// ---------------- 3. replace invalid entry embeddings with pad_token ----------------
__global__ void k_padfix(const float* __restrict__ pad_token) {
    int ba = blockIdx.x;
    int cnt = g_cnt[ba];
    float pv = pad_token[threadIdx.x];
    for (int s = cnt; s < cE; s++)
        g_e[((long long)ba * cE + s) * cHID + threadIdx.x] = pv;
}

// ---------------- 4. attention: scores + softmax + alpha@V + swish ----------------
__global__ void k_attn(const float* __restrict__ conn) {
    int gid = blockIdx.x;
    int a = gid % cA;
    int nb = gid / cA;
    int b = nb % cB, n = nb / cB;
    long long base = (((long long)n * cB + b) * cA) * cHID;
    const float* Qr = g_Qb + base + (long long)a * cHID;
    const float* Kb = g_Kb + base;
    const float* Vb = g_Vb + base;

    __shared__ float sQ[cHID];
    __shared__ float sAl[cA];
    __shared__ float sred[8];
    __shared__ float sstat;

    int tid = threadIdx.x, lane = tid & 31, w = tid >> 5;
    sQ[tid] = Qr[tid];
    __syncthreads();

    // scores: warp-parallel dot products (all 256 threads busy)
    for (int c = w; c < cA; c += 8) {
        const float* Kr = Kb + (long long)c * cHID;
        float p = 0.f;
#pragma unroll
        for (int i = lane; i < cHID; i += 32) p += sQ[i] * Kr[i];
        p = warpSum(p);
        if (lane == 0) sAl[c] = p * 0.0625f + conn[a * cA + c];
    }
    __syncthreads();

    float mval = -1e30f;
    for (int c = tid; c < cA; c += 256) mval = fmaxf(mval, sAl[c]);
    mval = warpMax(mval);
    if (lane == 0) sred[w] = mval;
    __syncthreads();
    if (tid == 0) {
        float mm = -1e30f;
#pragma unroll
        for (int i = 0; i < 8; i++) mm = fmaxf(mm, sred[i]);
        sstat = mm;
    }
    __syncthreads();
    float gmax = sstat;
    float psum = 0.f;
    for (int c = tid; c < cA; c += 256) {
        float ev = expf(sAl[c] - gmax);
        sAl[c] = ev;
        psum += ev;
    }
    psum = warpSum(psum);
    __syncthreads();
    if (lane == 0) sred[w] = psum;
    __syncthreads();
    if (tid == 0) {
        float tot = 0.f;
#pragma unroll
        for (int i = 0; i < 8; i++) tot += sred[i];
        sstat = tot;
    }
    __syncthreads();
    float inv = 1.f / sstat;

    float acc = 0.f;
#pragma unroll 4
    for (int c = 0; c < cA; c++) acc += sAl[c] * Vb[(long long)c * cHID + tid];
    acc *= inv;
    g_Hs[base + (long long)a * cHID + tid] = swishf(acc);
}

// ---------------- 5. layernorm per head + mean over heads -> h ----------------
__global__ void k_ln(const float* __restrict__ lnG, const float* __restrict__ lnB) {
    int m = blockIdx.x;
    int tid = threadIdx.x, lane = tid & 31, w = tid >> 5;
    __shared__ float sred[8];
    __shared__ float sval;
    float hacc = 0.f;
    for (int n = 0; n < cNH; n++) {
        float t = g_t2[((long long)n * cBA + m) * cHID + tid];
        float s = warpSum(t);
        if (lane == 0) sred[w] = s;
        __syncthreads();
        if (tid == 0) {
            float tot = 0.f;
#pragma unroll
            for (int i = 0; i < 8; i++) tot += sred[i];
            sval = tot * (1.f / cHID);
        }
        __syncthreads();
        float mean = sval;
        float d = t - mean;
        float s2 = warpSum(d * d);
        __syncthreads();
        if (lane == 0) sred[w] = s2;
        __syncthreads();
        if (tid == 0) {
            float tot = 0.f;
#pragma unroll
            for (int i = 0; i < 8; i++) tot += sred[i];
            sval = rsqrtf(tot * (1.f / cHID) + 1e-5f);
        }
        __syncthreads();
        hacc += d * sval * lnG[n * cHID + tid] + lnB[n * cHID + tid];
        __syncthreads();
    }
    g_h[(long long)m * cHID + tid] = hacc * 0.25f;
}

// ---------------- host-side launch helpers ----------------
template <bool SW>
static void tg128(const float* A, const float* B, const float* bias, float* C,
                  int M, int N, int K,
                  long long sA = 0, long long sB = 0, long long sb = 0, long long sC = 0,
                  int batch = 1, int lda = -1, int ldb = -1) {
    if (lda < 0) lda = K;
    if (ldb < 0) ldb = K;
    dim3 grid((N + 127) / 128, (M + 127) / 128, batch);
    k_tgemm<128, 128, 2, 4, SW><<<grid, 256>>>(A, B, bias, C, M, N, K, lda, ldb, sA, sB, sb, sC);
}
template <bool SW>
static void tg64(const float* A, const float* B, const float* bias, float* C,
                 int M, int N, int K,
                 long long sA = 0, long long sB = 0, long long sb = 0, long long sC = 0,
                 int batch = 1, int lda = -1, int ldb = -1) {
    if (lda < 0) lda = K;
    if (ldb < 0) ldb = K;
    dim3 grid((N + 63) / 64, (M + 63) / 64, batch);
    k_tgemm<64, 64, 2, 2, SW><<<grid, 128>>>(A, B, bias, C, M, N, K, lda, ldb, sA, sB, sb, sC);
}

extern "C" void kernel_launch(void* const* d_in, const int* in_sizes, int n_in,
                              void* d_out, int out_size) {
    const float* x       = (const float*)d_in[0];
    const float* fourier = (const float*)d_in[1];
    const float* encW1   = (const float*)d_in[2];
    const float* encB1   = (const float*)d_in[3];
    const float* encW2   = (const float*)d_in[4];
    const float* encB2   = (const float*)d_in[5];
    const float* padTok  = (const float*)d_in[6];
    const float* compW1  = (const float*)d_in[7];
    const float* compB1  = (const float*)d_in[8];
    const float* compW2  = (const float*)d_in[9];
    const float* compB2  = (const float*)d_in[10];
    const float* conn    = (const float*)d_in[11];
    const float* qW      = (const float*)d_in[12];
    const float* kW      = (const float*)d_in[13];
    const float* vW      = (const float*)d_in[14];
    const float* fpW1    = (const float*)d_in[15];
    const float* fpB1    = (const float*)d_in[16];
    const float* fpW2    = (const float*)d_in[17];
    const float* fpB2    = (const float*)d_in[18];
    const float* lnG     = (const float*)d_in[19];
    const float* lnB     = (const float*)d_in[20];
    const float* outW    = (const float*)d_in[21];
    const float* outB    = (const float*)d_in[22];
    float* out = (float*)d_out;

    float *pFeat, *pH1, *pE, *pCK, *pC1, *pH, *pQ, *pK, *pV, *pHs, *pT1, *pT2;
    cudaGetSymbolAddress((void**)&pFeat, g_feat);
    cudaGetSymbolAddress((void**)&pH1,   g_H1);
    cudaGetSymbolAddress((void**)&pE,    g_e);
    cudaGetSymbolAddress((void**)&pCK,   g_ck);
    cudaGetSymbolAddress((void**)&pC1,   g_c1);
    cudaGetSymbolAddress((void**)&pH,    g_h);
    cudaGetSymbolAddress((void**)&pQ,    g_Qb);
    cudaGetSymbolAddress((void**)&pK,    g_Kb);
    cudaGetSymbolAddress((void**)&pV,    g_Vb);
    cudaGetSymbolAddress((void**)&pHs,   g_Hs);
    cudaGetSymbolAddress((void**)&pT1,   g_t1);
    cudaGetSymbolAddress((void**)&pT2,   g_t2);

    // entry gather + features
    k_gather<<<cBA, 256>>>(x);
    k_feat<<<(cSLOTS + 255) / 256, 256>>>(fourier);

    // entry encoder MLP (bf16x2 tensor cores; K=33 -> scalar-load path)
    tg128<true >(pFeat, encW1, encB1, pH1, cSLOTS, cHID, cFEAT);
    tg128<false>(pH1,   encW2, encB2, pE,  cSLOTS, cHID, cHID);
    k_padfix<<<cBA, 256>>>(padTok);

    // per-agent compression: split-K=4 into partials, then fused reduce+bias+swish
    tg128<false>(pE, compW1, nullptr, pCK, cBA, 2 * cHID, cKCH,
                 /*sA=*/cKCH, /*sB=*/cKCH, 0, /*sC=*/(long long)cBA * 2 * cHID,
                 /*batch=*/cKS, /*lda=*/cE * cHID, /*ldb=*/cE * cHID);
    k_red<<<(cBA * 2 * cHID + 255) / 256, 256>>>(pCK, compB1, pC1);
    tg64<false>(pC1, compW2, compB2, pH, cBA, cHID, 2 * cHID);

    // message passing
    const long long sW = (long long)cHID * cHID;
    const long long sM = (long long)cBA * cHID;
    for (int s = 0; s < cSTEPS; s++) {
        tg128<false>(pH, qW, nullptr, pQ, cBA, cHID, cHID, 0, sW, 0, sM, cNH);
        tg128<false>(pH, kW, nullptr, pK, cBA, cHID, cHID, 0, sW, 0, sM, cNH);
        tg128<false>(pH, vW, nullptr, pV, cBA, cHID, cHID, 0, sW, 0, sM, cNH);
        k_attn<<<cNH * cBA, 256>>>(conn);
        tg128<true >(pHs, fpW1, fpB1, pT1, cBA, cHID, cHID, sM, sW, cHID, sM, cNH);
        tg128<false>(pT1, fpW2, fpB2, pT2, cBA, cHID, cHID, sM, sW, cHID, sM, cNH);
        k_ln<<<cBA, 256>>>(lnG, lnB);
    }

    // output projection
    tg128<false>(pH, outW, outB, out, cBA, cOUT, cHID);
}

// round 11
// speedup vs baseline: 3.3494x; 1.3165x over previous
#include <cuda_runtime.h>
#include <cuda_bf16.h>
#include <math.h>

// ---------------- problem constants ----------------
#define cB    32
#define cA    100
#define cD    10000
#define cHID  256
#define cNH   4
#define cOUT  10000
#define cNF   16
#define cE    100
#define cN    100
#define cFEAT 33          // 1 + 2*NFREQ
#define cFP   48          // padded feature K (multiple of 16)
#define cBA   (cB*cA)     // 3200
#define cSLOTS (cBA*cE)   // 320000
#define cSTEPS 3
#define cKS   4           // split-K factor for comp1
#define cKCH  (cE*cHID/cKS)   // 6400

// plane sizes (words = elements/2) for packed hi/lo bf16 buffers
#define P_FEAT ((long long)cSLOTS*(cFP/2))
#define P_H1   ((long long)cSLOTS*(cHID/2))
#define P_E    ((long long)cSLOTS*(cHID/2))
#define P_C1   ((long long)cBA*cHID)          // 3200 x 512 -> 256 w/row
#define P_H    ((long long)cBA*(cHID/2))
#define P_HS   ((long long)cNH*cBA*(cHID/2))
#define P_T1   P_HS

// ---------------- scratch (device globals; no allocs allowed) ----------------
__device__ int      g_cnt[cBA];
__device__ int      g_idx[cSLOTS];
__device__ float    g_val[cSLOTS];
__device__ unsigned g_featP[2*P_FEAT];
__device__ unsigned g_H1P [2*P_H1];
__device__ unsigned g_eP  [2*P_E];
__device__ float    g_ck  [cKS*cBA*2*cHID];   // split-K fp32 partials for comp1
__device__ unsigned g_c1P [2*P_C1];
__device__ unsigned g_hP  [2*P_H];
__device__ float    g_Qb [cNH*cBA*cHID];
__device__ float    g_Kb [cNH*cBA*cHID];
__device__ float    g_Vb [cNH*cBA*cHID];
__device__ unsigned g_HsP[2*P_HS];
__device__ unsigned g_t1P[2*P_T1];
__device__ float    g_t2 [cNH*cBA*cHID];
// packed weights
__device__ unsigned g_encW1P[2*256*(cFP/2)];
__device__ unsigned g_encW2P[2*256*128];
__device__ unsigned g_compW1P[2*(long long)512*12800];
__device__ unsigned g_compW2P[2*256*256];
__device__ unsigned g_qWP [2*1024*128];
__device__ unsigned g_kWP [2*1024*128];
__device__ unsigned g_vWP [2*1024*128];
__device__ unsigned g_fp1WP[2*1024*128];
__device__ unsigned g_fp2WP[2*1024*128];
__device__ unsigned g_outWP[2*(long long)cOUT*128];

// ---------------- helpers ----------------
__device__ __forceinline__ float swishf(float v) { return v / (1.f + expf(-v)); }

__device__ __forceinline__ float warpSum(float v) {
#pragma unroll
    for (int o = 16; o > 0; o >>= 1) v += __shfl_xor_sync(0xffffffffu, v, o);
    return v;
}
__device__ __forceinline__ float warpMax(float v) {
#pragma unroll
    for (int o = 16; o > 0; o >>= 1) v = fmaxf(v, __shfl_xor_sync(0xffffffffu, v, o));
    return v;
}

// pack two floats -> (hi bf16 pair word, lo bf16 pair word); low 16 bits = lower index
__device__ __forceinline__ void pack2(float x0, float x1, unsigned& hi, unsigned& lo) {
    __nv_bfloat16 h0 = __float2bfloat16_rn(x0);
    __nv_bfloat16 h1 = __float2bfloat16_rn(x1);
    float r0 = x0 - __bfloat162float(h0);
    float r1 = x1 - __bfloat162float(h1);
    __nv_bfloat16 l0 = __float2bfloat16_rn(r0);
    __nv_bfloat16 l1 = __float2bfloat16_rn(r1);
    hi = ((unsigned)__bfloat16_as_ushort(h1) << 16) | (unsigned)__bfloat16_as_ushort(h0);
    lo = ((unsigned)__bfloat16_as_ushort(l1) << 16) | (unsigned)__bfloat16_as_ushort(l0);
}

// split one float into hi/lo bf16 bit patterns (for shfl-pair packing)
__device__ __forceinline__ void split1(float x, unsigned& h, unsigned& l) {
    __nv_bfloat16 hb = __float2bfloat16_rn(x);
    float r = x - __bfloat162float(hb);
    __nv_bfloat16 lb = __float2bfloat16_rn(r);
    h = (unsigned)__bfloat16_as_ushort(hb);
    l = (unsigned)__bfloat16_as_ushort(lb);
}

// one m16n8k16 bf16 mma, fp32 accumulate
__device__ __forceinline__ void mma16(float* c, const unsigned* a, const unsigned* b) {
    asm volatile(
        "mma.sync.aligned.m16n8k16.row.col.f32.bf16.bf16.f32 "
        "{%0,%1,%2,%3}, {%4,%5,%6,%7}, {%8,%9}, {%0,%1,%2,%3};"
        : "+f"(c[0]), "+f"(c[1]), "+f"(c[2]), "+f"(c[3])
        : "r"(a[0]), "r"(a[1]), "r"(a[2]), "r"(a[3]), "r"(b[0]), "r"(b[1]));
}

// ---------------- weight pack: fp32 [rows x Kin] -> packed [rows x KoutW words] x2 planes ----------------
__global__ void k_pack(const float* __restrict__ W, unsigned* __restrict__ P,
                       int rows, int Kin, int KoutW, long long plane) {
    long long i = (long long)blockIdx.x * 256 + threadIdx.x;
    if (i >= (long long)rows * KoutW) return;
    int r = (int)(i / KoutW), j = (int)(i % KoutW);
    int k = 2 * j;
    float a = (k     < Kin) ? W[(long long)r * Kin + k]     : 0.f;
    float b = (k + 1 < Kin) ? W[(long long)r * Kin + k + 1] : 0.f;
    unsigned hi, lo;
    pack2(a, b, hi, lo);
    P[i] = hi;
    P[i + plane] = lo;
}

// ---------------- 1. ragged gather of nonzeros (stable, ascending) ----------------
__global__ void k_gather(const float* __restrict__ x) {
    int m = blockIdx.x;
    const float* xr = x + (long long)m * cD;
    int tid = threadIdx.x, lane = tid & 31, w = tid >> 5;
    __shared__ int warp_cnt[8];
    __shared__ int s_base;
    if (tid == 0) s_base = 0;
    __syncthreads();
    for (int c0 = 0; c0 < cD; c0 += 256) {
        int i = c0 + tid;
        float v = (i < cD) ? xr[i] : 0.f;
        bool nz = (i < cD) && (v != 0.f);
        unsigned ball = __ballot_sync(0xffffffffu, nz);
        int wpre = __popc(ball & ((1u << lane) - 1u));
        if (lane == 0) warp_cnt[w] = __popc(ball);
        __syncthreads();
        int off = 0;
#pragma unroll
        for (int ww = 0; ww < 8; ++ww) if (ww < w) off += warp_cnt[ww];
        int total = 0;
#pragma unroll
        for (int ww = 0; ww < 8; ++ww) total += warp_cnt[ww];
        int pos = s_base + off + wpre;
        if (nz && pos < cE) { g_idx[m * cE + pos] = i; g_val[m * cE + pos] = v; }
        __syncthreads();
        if (tid == 0) s_base += total;
        __syncthreads();
    }
    int cnt = min(s_base, cE);
    if (tid == 0) g_cnt[m] = cnt;
    for (int s = cnt + tid; s < cE; s += 256) { g_idx[m * cE + s] = 0; g_val[m * cE + s] = 0.f; }
}

// ---------------- 2. Fourier features -> packed feat [slot][48] ----------------
__global__ void k_featP(const float* __restrict__ fourierB) {
    long long slot = (long long)blockIdx.x * blockDim.x + threadIdx.x;
    if (slot >= cSLOTS) return;
    int idx = g_idx[slot];
    float val = g_val[slot];
    float row = (float)(idx / cN), col = (float)(idx % cN);
    float f[cFP];
    f[0] = val;
#pragma unroll
    for (int k = 0; k < cNF; k++) {
        float t = row * fourierB[2 * k] + col * fourierB[2 * k + 1];
        f[1 + k]       = sinpif(2.f * t);
        f[1 + cNF + k] = cospif(2.f * t);
    }
#pragma unroll
    for (int j = cFEAT; j < cFP; j++) f[j] = 0.f;
    long long base = slot * (cFP / 2);
#pragma unroll
    for (int j = 0; j < cFP / 2; j++) {
        unsigned hi, lo;
        pack2(f[2 * j], f[2 * j + 1], hi, lo);
        g_featP[base + j] = hi;
        g_featP[P_FEAT + base + j] = lo;
    }
}

// ---------------- bf16x2 tensor-core GEMM on pre-packed operands ----------------
// C = act(A[M,K] @ B[N,K]^T + bias); A,B packed hi/lo bf16 planes (pair words along k).
// K multiple of 16 guaranteed. BK=16, double buffered, smem stride 20 words.
// Output: fp32 (Cf) or packed hi/lo (Cp) per template flag.
template <int TM, int TN, int WM, int WN, bool SWISH, bool PACKOUT>
__global__ void __launch_bounds__(WM * WN * 32, (WM * WN * 32 >= 256) ? 2 : 4)
k_tgemm(const unsigned* __restrict__ Ah, const unsigned* __restrict__ Bh,
        const float* __restrict__ bias,
        float* __restrict__ Cf, unsigned* __restrict__ Cp,
        int M, int Nn, int Kw, int ldaw, int ldbw,
        long long plA, long long plB, long long plC,
        long long sA_, long long sB_, long long sBias, long long sC) {
    constexpr int THREADS = WM * WN * 32;
    constexpr int MT = TM / WM / 16;
    constexpr int NT = TN / WN / 8;
    constexpr int WS = 20;

    __shared__ unsigned shA[2][TM * WS];
    __shared__ unsigned shB[2][TN * WS];

    int z = blockIdx.z;
    const unsigned* Al = Ah + plA + (long long)z * sA_;
    const unsigned* Bl = Bh + plB + (long long)z * sB_;
    Ah += (long long)z * sA_;
    Bh += (long long)z * sB_;
    if (Cf) Cf += (long long)z * sC;
    if (Cp) Cp += (long long)z * sC;
    const float* bptr = bias ? bias + (long long)z * sBias : nullptr;

    int tid = threadIdx.x;
    int m0 = blockIdx.y * TM, n0 = blockIdx.x * TN;
    int wid = tid >> 5, lane = tid & 31;
    int wm = wid / WN, wn = wid % WN;
    int g = lane >> 2, tg = lane & 3;

    float acc[MT][NT][4];
#pragma unroll
    for (int mt = 0; mt < MT; mt++)
#pragma unroll
        for (int nt = 0; nt < NT; nt++)
#pragma unroll
            for (int i = 0; i < 4; i++) acc[mt][nt][i] = 0.f;

    int nK = Kw / 8;   // k16 steps

    auto load = [&](int k0w, int b) {
#pragma unroll 2
        for (int qi = tid; qi < TM * 4; qi += THREADS) {
            int r = qi >> 2, q = qi & 3;               // q<2: hi half0/1, q>=2: lo
            int gm = m0 + r;
            const unsigned* src = (q < 2) ? Ah : Al;
            uint4 v = make_uint4(0u, 0u, 0u, 0u);
            if (gm < M)
                v = *(const uint4*)(src + (long long)gm * ldaw + k0w + ((q & 1) << 2));
            *(uint4*)&shA[b][r * WS + ((q >= 2) ? 8 : 0) + ((q & 1) << 2)] = v;
        }
#pragma unroll 2
        for (int qi = tid; qi < TN * 4; qi += THREADS) {
            int r = qi >> 2, q = qi & 3;
            int gn = n0 + r;
            const unsigned* src = (q < 2) ? Bh : Bl;
            uint4 v = make_uint4(0u, 0u, 0u, 0u);
            if (gn < Nn)
                v = *(const uint4*)(src + (long long)gn * ldbw + k0w + ((q & 1) << 2));
            *(uint4*)&shB[b][r * WS + ((q >= 2) ? 8 : 0) + ((q & 1) << 2)] = v;
        }
    };

    auto compute = [&](int b) {
        const unsigned* sa = shA[b];
        const unsigned* sb = shB[b];
        unsigned bhi[NT][2], blo[NT][2];
#pragma unroll
        for (int nt = 0; nt < NT; nt++) {
            int col = (wn * NT + nt) * 8 + g;
            const unsigned* p = sb + col * WS;
            bhi[nt][0] = p[tg];     bhi[nt][1] = p[tg + 4];
            blo[nt][0] = p[tg + 8]; blo[nt][1] = p[tg + 12];
        }
#pragma unroll
        for (int mt = 0; mt < MT; mt++) {
            int row = (wm * MT + mt) * 16;
            const unsigned* p0 = sa + (row + g) * WS;
            const unsigned* p1 = sa + (row + g + 8) * WS;
            unsigned ahi[4], alo[4];
            ahi[0] = p0[tg];     ahi[1] = p1[tg];     ahi[2] = p0[tg + 4];  ahi[3] = p1[tg + 4];
            alo[0] = p0[tg + 8]; alo[1] = p1[tg + 8]; alo[2] = p0[tg + 12]; alo[3] = p1[tg + 12];
#pragma unroll
            for (int nt = 0; nt < NT; nt++) {
                mma16(acc[mt][nt], ahi, bhi[nt]);
                mma16(acc[mt][nt], ahi, blo[nt]);
                mma16(acc[mt][nt], alo, bhi[nt]);
            }
        }
    };

    load(0, 0);
    __syncthreads();
    int buf = 0;
    for (int it = 0; it < nK; it++) {
        if (it + 1 < nK) load((it + 1) * 8, buf ^ 1);
        compute(buf);
        __syncthreads();
        buf ^= 1;
    }

    // epilogue: acc i=0:(g,2tg) i=1:(g,2tg+1) i=2:(g+8,2tg) i=3:(g+8,2tg+1)
#pragma unroll
    for (int mt = 0; mt < MT; mt++) {
        int r0 = m0 + (wm * MT + mt) * 16;
#pragma unroll
        for (int nt = 0; nt < NT; nt++) {
            int gn0 = n0 + (wn * NT + nt) * 8 + 2 * tg;
            if (PACKOUT) {
                float b0 = bptr ? bptr[gn0] : 0.f;
                float b1 = bptr ? bptr[gn0 + 1] : 0.f;
                int ldcw = Nn >> 1;
                long long wj = (gn0 >> 1);
#pragma unroll
                for (int half = 0; half < 2; half++) {
                    int gm = r0 + g + half * 8;
                    if (gm < M && gn0 + 1 < Nn) {
                        float v0 = acc[mt][nt][2 * half]     + b0;
                        float v1 = acc[mt][nt][2 * half + 1] + b1;
                        if (SWISH) { v0 = swishf(v0); v1 = swishf(v1); }
                        unsigned hi, lo;
                        pack2(v0, v1, hi, lo);
                        long long o = (long long)gm * ldcw + wj;
                        Cp[o] = hi;
                        Cp[o + plC] = lo;
                    }
                }
            } else {
#pragma unroll
                for (int i = 0; i < 4; i++) {
                    int gm = r0 + g + (i >> 1) * 8;
                    int gn = gn0 + (i & 1);
                    if (gm < M && gn < Nn) {
                        float v = acc[mt][nt][i] + (bptr ? bptr[gn] : 0.f);
                        if (SWISH) v = swishf(v);
                        Cf[(long long)gm * Nn + gn] = v;
                    }
                }
            }
        }
    }
}

// ---------------- split-K reduce for comp1 -> packed c1 ----------------
__global__ void k_redP(const float* __restrict__ part, const float* __restrict__ bias) {
    long long i = (long long)blockIdx.x * 256 + threadIdx.x;   // word index
    if (i >= P_C1) return;
    const long long MN = (long long)cBA * 2 * cHID;
    int j = (int)(i % (cHID));        // word within row (256 words = 512 cols)
    long long e = 2 * i;              // element index of col 2j in row-major c1
    float s0 = part[e]     + part[e + MN]     + part[e + 2 * MN]     + part[e + 3 * MN]     + bias[2 * j];
    float s1 = part[e + 1] + part[e + 1 + MN] + part[e + 1 + 2 * MN] + part[e + 1 + 3 * MN] + bias[2 * j + 1];
    unsigned hi, lo;
    pack2(swishf(s0), swishf(s1), hi, lo);
    g_c1P[i] = hi;
    g_c1P[P_C1 + i] = lo;
}

// ---------------- 3. pad slots -> packed pad_token rows in eP ----------------
__global__ void k_padfixP(const float* __restrict__ pad_token) {
    int ba = blockIdx.x;
    int j = threadIdx.x;               // 128 threads, one pair word each
    int cnt = g_cnt[ba];
    unsigned hi, lo;
    pack2(pad_token[2 * j], pad_token[2 * j + 1], hi, lo);
    for (int s = cnt; s < cE; s++) {
        long long o = ((long long)ba * cE + s) * (cHID / 2) + j;
        g_eP[o] = hi;
        g_eP[P_E + o] = lo;
    }
}

// ---------------- 4. attention: scores + softmax + alpha@V + swish -> packed Hs ----------------
__global__ void k_attn(const float* __restrict__ conn) {
    int gid = blockIdx.x;
    int a = gid % cA;
    int nb = gid / cA;
    int b = nb % cB, n = nb / cB;
    long long base = (((long long)n * cB + b) * cA) * cHID;
    const float* Qr = g_Qb + base + (long long)a * cHID;
    const float* Kb = g_Kb + base;
    const float* Vb = g_Vb + base;

    __shared__ float sQ[cHID];
    __shared__ float sAl[cA];
    __shared__ float sred[8];
    __shared__ float sstat;

    int tid = threadIdx.x, lane = tid & 31, w = tid >> 5;
    sQ[tid] = Qr[tid];
    __syncthreads();

    for (int c = w; c < cA; c += 8) {
        const float* Kr = Kb + (long long)c * cHID;
        float p = 0.f;
#pragma unroll
        for (int i = lane; i < cHID; i += 32) p += sQ[i] * Kr[i];
        p = warpSum(p);
        if (lane == 0) sAl[c] = p * 0.0625f + conn[a * cA + c];
    }
    __syncthreads();

    float mval = -1e30f;
    for (int c = tid; c < cA; c += 256) mval = fmaxf(mval, sAl[c]);
    mval = warpMax(mval);
    if (lane == 0) sred[w] = mval;
    __syncthreads();
    if (tid == 0) {
        float mm = -1e30f;
#pragma unroll
        for (int i = 0; i < 8; i++) mm = fmaxf(mm, sred[i]);
        sstat = mm;
    }
    __syncthreads();
    float gmax = sstat;
    float psum = 0.f;
    for (int c = tid; c < cA; c += 256) {
        float ev = expf(sAl[c] - gmax);
        sAl[c] = ev;
        psum += ev;
    }
    psum = warpSum(psum);
    __syncthreads();
    if (lane == 0) sred[w] = psum;
    __syncthreads();
    if (tid == 0) {
        float tot = 0.f;
#pragma unroll
        for (int i = 0; i < 8; i++) tot += sred[i];
        sstat = tot;
    }
    __syncthreads();
    float inv = 1.f / sstat;

    float acc = 0.f;
#pragma unroll 4
    for (int c = 0; c < cA; c++) acc += sAl[c] * Vb[(long long)c * cHID + tid];
    float v = swishf(acc * inv);

    // pair-pack adjacent columns via shfl and store packed Hs
    unsigned h16, l16;
    split1(v, h16, l16);
    unsigned ho = __shfl_down_sync(0xffffffffu, h16, 1);
    unsigned lo = __shfl_down_sync(0xffffffffu, l16, 1);
    if (!(tid & 1)) {
        long long rb = ((((long long)n * cB + b) * cA) + a) * (cHID / 2) + (tid >> 1);
        g_HsP[rb] = (ho << 16) | h16;
        g_HsP[P_HS + rb] = (lo << 16) | l16;
    }
}

// ---------------- 5. layernorm per head + mean over heads -> packed h ----------------
__global__ void k_ln(const float* __restrict__ lnG, const float* __restrict__ lnB) {
    int m = blockIdx.x;
    int tid = threadIdx.x, lane = tid & 31, w = tid >> 5;
    __shared__ float sred[8];
    __shared__ float sval;
    float hacc = 0.f;
    for (int n = 0; n < cNH; n++) {
        float t = g_t2[((long long)n * cBA + m) * cHID + tid];
        float s = warpSum(t);
        if (lane == 0) sred[w] = s;
        __syncthreads();
        if (tid == 0) {
            float tot = 0.f;
#pragma unroll
            for (int i = 0; i < 8; i++) tot += sred[i];
            sval = tot * (1.f / cHID);
        }
        __syncthreads();
        float mean = sval;
        float d = t - mean;
        float s2 = warpSum(d * d);
        __syncthreads();
        if (lane == 0) sred[w] = s2;
        __syncthreads();
        if (tid == 0) {
            float tot = 0.f;
#pragma unroll
            for (int i = 0; i < 8; i++) tot += sred[i];
            sval = rsqrtf(tot * (1.f / cHID) + 1e-5f);
        }
        __syncthreads();
        hacc += d * sval * lnG[n * cHID + tid] + lnB[n * cHID + tid];
        __syncthreads();
    }
    float v = hacc * 0.25f;
    unsigned h16, l16;
    split1(v, h16, l16);
    unsigned ho = __shfl_down_sync(0xffffffffu, h16, 1);
    unsigned lo = __shfl_down_sync(0xffffffffu, l16, 1);
    if (!(tid & 1)) {
        long long rb = (long long)m * (cHID / 2) + (tid >> 1);
        g_hP[rb] = (ho << 16) | h16;
        g_hP[P_H + rb] = (lo << 16) | l16;
    }
}

// ---------------- host-side launch helper ----------------
template <int TM, int TN, int WM, int WN, bool SW, bool PK>
static void tg(const unsigned* Ah, const unsigned* Bh, const float* bias,
               float* Cf, unsigned* Cp,
               int M, int N, int Kw, int ldaw, int ldbw,
               long long plA, long long plB, long long plC,
               long long sA = 0, long long sB = 0, long long sb = 0, long long sC = 0,
               int batch = 1) {
    dim3 grid((N + TN - 1) / TN, (M + TM - 1) / TM, batch);
    k_tgemm<TM, TN, WM, WN, SW, PK><<<grid, WM * WN * 32>>>(
        Ah, Bh, bias, Cf, Cp, M, N, Kw, ldaw, ldbw, plA, plB, plC, sA, sB, sb, sC);
}

extern "C" void kernel_launch(void* const* d_in, const int* in_sizes, int n_in,
                              void* d_out, int out_size) {
    const float* x       = (const float*)d_in[0];
    const float* fourier = (const float*)d_in[1];
    const float* encW1   = (const float*)d_in[2];
    const float* encB1   = (const float*)d_in[3];
    const float* encW2   = (const float*)d_in[4];
    const float* encB2   = (const float*)d_in[5];
    const float* padTok  = (const float*)d_in[6];
    const float* compW1  = (const float*)d_in[7];
    const float* compB1  = (const float*)d_in[8];
    const float* compW2  = (const float*)d_in[9];
    const float* compB2  = (const float*)d_in[10];
    const float* conn    = (const float*)d_in[11];
    const float* qW      = (const float*)d_in[12];
    const float* kW      = (const float*)d_in[13];
    const float* vW      = (const float*)d_in[14];
    const float* fpW1    = (const float*)d_in[15];
    const float* fpB1    = (const float*)d_in[16];
    const float* fpW2    = (const float*)d_in[17];
    const float* fpB2    = (const float*)d_in[18];
    const float* lnG     = (const float*)d_in[19];
    const float* lnB     = (const float*)d_in[20];
    const float* outW    = (const float*)d_in[21];
    const float* outB    = (const float*)d_in[22];
    float* out = (float*)d_out;

    unsigned *pFeatP, *pH1P, *pEP, *pC1P, *pHP, *pHsP, *pT1P;
    unsigned *pW1, *pW2, *pCW1, *pCW2, *pQW, *pKW, *pVW, *pF1W, *pF2W, *pOW;
    float *pCK, *pQ, *pKb, *pVb, *pT2;
    cudaGetSymbolAddress((void**)&pFeatP, g_featP);
    cudaGetSymbolAddress((void**)&pH1P,   g_H1P);
    cudaGetSymbolAddress((void**)&pEP,    g_eP);
    cudaGetSymbolAddress((void**)&pC1P,   g_c1P);
    cudaGetSymbolAddress((void**)&pHP,    g_hP);
    cudaGetSymbolAddress((void**)&pHsP,   g_HsP);
    cudaGetSymbolAddress((void**)&pT1P,   g_t1P);
    cudaGetSymbolAddress((void**)&pW1,    g_encW1P);
    cudaGetSymbolAddress((void**)&pW2,    g_encW2P);
    cudaGetSymbolAddress((void**)&pCW1,   g_compW1P);
    cudaGetSymbolAddress((void**)&pCW2,   g_compW2P);
    cudaGetSymbolAddress((void**)&pQW,    g_qWP);
    cudaGetSymbolAddress((void**)&pKW,    g_kWP);
    cudaGetSymbolAddress((void**)&pVW,    g_vWP);
    cudaGetSymbolAddress((void**)&pF1W,   g_fp1WP);
    cudaGetSymbolAddress((void**)&pF2W,   g_fp2WP);
    cudaGetSymbolAddress((void**)&pOW,    g_outWP);
    cudaGetSymbolAddress((void**)&pCK,    g_ck);
    cudaGetSymbolAddress((void**)&pQ,     g_Qb);
    cudaGetSymbolAddress((void**)&pKb,    g_Kb);
    cudaGetSymbolAddress((void**)&pVb,    g_Vb);
    cudaGetSymbolAddress((void**)&pT2,    g_t2);

    auto packW = [&](const float* W, unsigned* P, int rows, int Kin, int KoutW) {
        long long tot = (long long)rows * KoutW;
        k_pack<<<(unsigned)((tot + 255) / 256), 256>>>(W, P, rows, Kin, KoutW, tot);
    };

    // one-shot weight packing (cheap; runs per call, deterministic)
    packW(encW1, pW1, 256, cFEAT, cFP / 2);
    packW(encW2, pW2, 256, 256, 128);
    packW(compW1, pCW1, 512, 25600, 12800);
    packW(compW2, pCW2, 256, 512, 256);
    packW(qW,   pQW,  1024, 256, 128);
    packW(kW,   pKW,  1024, 256, 128);
    packW(vW,   pVW,  1024, 256, 128);
    packW(fpW1, pF1W, 1024, 256, 128);
    packW(fpW2, pF2W, 1024, 256, 128);
    packW(outW, pOW,  cOUT, 256, 128);

    // entry gather + packed features
    k_gather<<<cBA, 256>>>(x);
    k_featP<<<(cSLOTS + 255) / 256, 256>>>(fourier);

    // entry encoder MLP
    tg<128,128,2,4,true ,true >(pFeatP, pW1, encB1, nullptr, pH1P,
        cSLOTS, cHID, cFP / 2, cFP / 2, cFP / 2, P_FEAT, (long long)256 * (cFP / 2), P_H1);
    tg<128,128,2,4,false,true >(pH1P, pW2, encB2, nullptr, pEP,
        cSLOTS, cHID, 128, 128, 128, P_H1, 256 * 128, P_E);
    k_padfixP<<<cBA, 128>>>(padTok);

    // per-agent compression: split-K=4 partials (fp32) + fused packed reduce
    tg<128,128,2,4,false,false>(pEP, pCW1, nullptr, pCK, nullptr,
        cBA, 2 * cHID, cKCH / 2, 12800, 12800, P_E, (long long)512 * 12800, 0,
        /*sA=*/cKCH / 2, /*sB=*/cKCH / 2, 0, /*sC=*/(long long)cBA * 2 * cHID, cKS);
    k_redP<<<(unsigned)((P_C1 + 255) / 256), 256>>>(pCK, compB1);
    tg<64,64,2,2,false,true >(pC1P, pCW2, compB2, nullptr, pHP,
        cBA, cHID, 256, 256, 256, P_C1, (long long)256 * 256, P_H);

    // message passing
    const long long sWw = (long long)cHID * 128;   // per-head weight stride (words)
    const long long sMf = (long long)cBA * cHID;   // per-head fp32 act stride (elements)
    const long long sMw = (long long)cBA * 128;    // per-head packed act stride (words)
    for (int s = 0; s < cSTEPS; s++) {
        tg<128,128,2,4,false,false>(pHP, pQW, nullptr, pQ, nullptr,
            cBA, cHID, 128, 128, 128, P_H, (long long)1024 * 128, 0, 0, sWw, 0, sMf, cNH);
        tg<128,128,2,4,false,false>(pHP, pKW, nullptr, pKb, nullptr,
            cBA, cHID, 128, 128, 128, P_H, (long long)1024 * 128, 0, 0, sWw, 0, sMf, cNH);
        tg<128,128,2,4,false,false>(pHP, pVW, nullptr, pVb, nullptr,
            cBA, cHID, 128, 128, 128, P_H, (long long)1024 * 128, 0, 0, sWw, 0, sMf, cNH);
        k_attn<<<cNH * cBA, 256>>>(conn);
        tg<128,128,2,4,true ,true >(pHsP, pF1W, fpB1, nullptr, pT1P,
            cBA, cHID, 128, 128, 128, P_HS, (long long)1024 * 128, P_T1,
            sMw, sWw, cHID, sMw, cNH);
        tg<128,128,2,4,false,false>(pT1P, pF2W, fpB2, pT2, nullptr,
            cBA, cHID, 128, 128, 128, P_T1, (long long)1024 * 128, 0,
            sMw, sWw, cHID, sMf, cNH);
        k_ln<<<cBA, 256>>>(lnG, lnB);
    }

    // output projection
    tg<128,128,2,4,false,false>(pHP, pOW, outB, out, nullptr,
        cBA, cOUT, 128, 128, 128, P_H, (long long)cOUT * 128, 0);
}

// round 12
// speedup vs baseline: 3.5348x; 1.0554x over previous
#include <cuda_runtime.h>
#include <cuda_bf16.h>
#include <math.h>

// ---------------- problem constants ----------------
#define cB    32
#define cA    100
#define cD    10000
#define cHID  256
#define cNH   4
#define cOUT  10000
#define cNF   16
#define cE    100
#define cN    100
#define cFEAT 33          // 1 + 2*NFREQ
#define cFP   48          // padded feature K (multiple of 16)
#define cBA   (cB*cA)     // 3200
#define cSLOTS (cBA*cE)   // 320000
#define cSTEPS 3
#define cKS   4           // split-K factor for comp1
#define cKCH  (cE*cHID/cKS)   // 6400

// plane sizes (words = elements/2) for packed hi/lo bf16 buffers
#define P_FEAT ((long long)cSLOTS*(cFP/2))
#define P_H1   ((long long)cSLOTS*(cHID/2))
#define P_E    ((long long)cSLOTS*(cHID/2))
#define P_C1   ((long long)cBA*cHID)          // 3200 x 512 -> 256 w/row
#define P_H    ((long long)cBA*(cHID/2))
#define P_HS   ((long long)cNH*cBA*(cHID/2))
#define P_T1   P_HS
#define PL_QKV ((long long)4*768*128)         // fused qkv weight plane (words)

// ---------------- scratch (device globals; no allocs allowed) ----------------
__device__ int      g_cnt[cBA];
__device__ int      g_idx[cSLOTS];
__device__ float    g_val[cSLOTS];
__device__ unsigned g_featP[2*P_FEAT];
__device__ unsigned g_H1P [2*P_H1];
__device__ unsigned g_eP  [2*P_E];
__device__ float    g_ck  [cKS*cBA*2*cHID];   // split-K fp32 partials for comp1
__device__ unsigned g_c1P [2*P_C1];
__device__ unsigned g_hP  [2*P_H];
__device__ float    g_Qb [cNH*cBA*cHID];
__device__ float    g_Kb [cNH*cBA*cHID];
__device__ float    g_Vb [cNH*cBA*cHID];
__device__ unsigned g_HsP[2*P_HS];
__device__ unsigned g_t1P[2*P_T1];
__device__ float    g_t2 [cNH*cBA*cHID];
// packed weights
__device__ unsigned g_encW1P[2*256*(cFP/2)];
__device__ unsigned g_encW2P[2*256*128];
__device__ unsigned g_compW1P[2*(long long)512*12800];
__device__ unsigned g_compW2P[2*256*256];
__device__ unsigned g_qkvWP[2*PL_QKV];
__device__ unsigned g_fp1WP[2*1024*128];
__device__ unsigned g_fp2WP[2*1024*128];
__device__ unsigned g_outWP[2*(long long)cOUT*128];

// ---------------- helpers ----------------
__device__ __forceinline__ float swishf(float v) { return v / (1.f + expf(-v)); }

__device__ __forceinline__ float warpSum(float v) {
#pragma unroll
    for (int o = 16; o > 0; o >>= 1) v += __shfl_xor_sync(0xffffffffu, v, o);
    return v;
}
__device__ __forceinline__ float warpMax(float v) {
#pragma unroll
    for (int o = 16; o > 0; o >>= 1) v = fmaxf(v, __shfl_xor_sync(0xffffffffu, v, o));
    return v;
}

// pack two floats -> (hi bf16 pair word, lo bf16 pair word); low 16 bits = lower index
__device__ __forceinline__ void pack2(float x0, float x1, unsigned& hi, unsigned& lo) {
    __nv_bfloat16 h0 = __float2bfloat16_rn(x0);
    __nv_bfloat16 h1 = __float2bfloat16_rn(x1);
    float r0 = x0 - __bfloat162float(h0);
    float r1 = x1 - __bfloat162float(h1);
    __nv_bfloat16 l0 = __float2bfloat16_rn(r0);
    __nv_bfloat16 l1 = __float2bfloat16_rn(r1);
    hi = ((unsigned)__bfloat16_as_ushort(h1) << 16) | (unsigned)__bfloat16_as_ushort(h0);
    lo = ((unsigned)__bfloat16_as_ushort(l1) << 16) | (unsigned)__bfloat16_as_ushort(l0);
}

// split one float into hi/lo bf16 bit patterns (for shfl-pair packing)
__device__ __forceinline__ void split1(float x, unsigned& h, unsigned& l) {
    __nv_bfloat16 hb = __float2bfloat16_rn(x);
    float r = x - __bfloat162float(hb);
    __nv_bfloat16 lb = __float2bfloat16_rn(r);
    h = (unsigned)__bfloat16_as_ushort(hb);
    l = (unsigned)__bfloat16_as_ushort(lb);
}

// one m16n8k16 bf16 mma, fp32 accumulate
__device__ __forceinline__ void mma16(float* c, const unsigned* a, const unsigned* b) {
    asm volatile(
        "mma.sync.aligned.m16n8k16.row.col.f32.bf16.bf16.f32 "
        "{%0,%1,%2,%3}, {%4,%5,%6,%7}, {%8,%9}, {%0,%1,%2,%3};"
        : "+f"(c[0]), "+f"(c[1]), "+f"(c[2]), "+f"(c[3])
        : "r"(a[0]), "r"(a[1]), "r"(a[2]), "r"(a[3]), "r"(b[0]), "r"(b[1]));
}

__device__ __forceinline__ void ldsm4(unsigned& r0, unsigned& r1, unsigned& r2, unsigned& r3,
                                      unsigned addr) {
    asm volatile("ldmatrix.sync.aligned.m8n8.x4.shared.b16 {%0,%1,%2,%3}, [%4];"
        : "=r"(r0), "=r"(r1), "=r"(r2), "=r"(r3) : "r"(addr));
}
__device__ __forceinline__ void ldsm2(unsigned& r0, unsigned& r1, unsigned addr) {
    asm volatile("ldmatrix.sync.aligned.m8n8.x2.shared.b16 {%0,%1}, [%2];"
        : "=r"(r0), "=r"(r1) : "r"(addr));
}

// ---------------- weight pack: fp32 [rows x Kin] -> packed hi/lo planes ----------------
__global__ void k_pack(const float* __restrict__ W, unsigned* __restrict__ P,
                       int rows, int Kin, int KoutW, long long plane) {
    long long i = (long long)blockIdx.x * 256 + threadIdx.x;
    if (i >= (long long)rows * KoutW) return;
    int r = (int)(i / KoutW), j = (int)(i % KoutW);
    int k = 2 * j;
    float a = (k     < Kin) ? W[(long long)r * Kin + k]     : 0.f;
    float b = (k + 1 < Kin) ? W[(long long)r * Kin + k + 1] : 0.f;
    unsigned hi, lo;
    pack2(a, b, hi, lo);
    P[i] = hi;
    P[i + plane] = lo;
}

// pack q/k/v weights into one fused buffer: per head 768 rows (q 0-255, k 256-511, v 512-767)
__global__ void k_packQKV(const float* __restrict__ qW, const float* __restrict__ kW,
                          const float* __restrict__ vW, unsigned* __restrict__ P) {
    long long i = (long long)blockIdx.x * 256 + threadIdx.x;
    if (i >= PL_QKV) return;
    int j = (int)(i & 127);
    long long row = i >> 7;
    int n = (int)(row / 768);
    int rr = (int)(row % 768);
    int m = rr >> 8;
    int r = rr & 255;
    const float* W = (m == 0) ? qW : (m == 1) ? kW : vW;
    const float* src = W + ((long long)n * 256 + r) * 256 + 2 * j;
    unsigned hi, lo;
    pack2(src[0], src[1], hi, lo);
    P[i] = hi;
    P[i + PL_QKV] = lo;
}

// ---------------- 1. ragged gather of nonzeros (stable, ascending) ----------------
__global__ void k_gather(const float* __restrict__ x) {
    int m = blockIdx.x;
    const float* xr = x + (long long)m * cD;
    int tid = threadIdx.x, lane = tid & 31, w = tid >> 5;
    __shared__ int warp_cnt[8];
    __shared__ int s_base;
    if (tid == 0) s_base = 0;
    __syncthreads();
    for (int c0 = 0; c0 < cD; c0 += 256) {
        int i = c0 + tid;
        float v = (i < cD) ? xr[i] : 0.f;
        bool nz = (i < cD) && (v != 0.f);
        unsigned ball = __ballot_sync(0xffffffffu, nz);
        int wpre = __popc(ball & ((1u << lane) - 1u));
        if (lane == 0) warp_cnt[w] = __popc(ball);
        __syncthreads();
        int off = 0;
#pragma unroll
        for (int ww = 0; ww < 8; ++ww) if (ww < w) off += warp_cnt[ww];
        int total = 0;
#pragma unroll
        for (int ww = 0; ww < 8; ++ww) total += warp_cnt[ww];
        int pos = s_base + off + wpre;
        if (nz && pos < cE) { g_idx[m * cE + pos] = i; g_val[m * cE + pos] = v; }
        __syncthreads();
        if (tid == 0) s_base += total;
        __syncthreads();
    }
    int cnt = min(s_base, cE);
    if (tid == 0) g_cnt[m] = cnt;
    for (int s = cnt + tid; s < cE; s += 256) { g_idx[m * cE + s] = 0; g_val[m * cE + s] = 0.f; }
}

// ---------------- 2. Fourier features -> packed feat [slot][48] ----------------
__global__ void k_featP(const float* __restrict__ fourierB) {
    long long slot = (long long)blockIdx.x * blockDim.x + threadIdx.x;
    if (slot >= cSLOTS) return;
    int idx = g_idx[slot];
    float val = g_val[slot];
    float row = (float)(idx / cN), col = (float)(idx % cN);
    float f[cFP];
    f[0] = val;
#pragma unroll
    for (int k = 0; k < cNF; k++) {
        float t = row * fourierB[2 * k] + col * fourierB[2 * k + 1];
        f[1 + k]       = sinpif(2.f * t);
        f[1 + cNF + k] = cospif(2.f * t);
    }
#pragma unroll
    for (int j = cFEAT; j < cFP; j++) f[j] = 0.f;
    long long base = slot * (cFP / 2);
#pragma unroll
    for (int j = 0; j < cFP / 2; j++) {
        unsigned hi, lo;
        pack2(f[2 * j], f[2 * j + 1], hi, lo);
        g_featP[base + j] = hi;
        g_featP[P_FEAT + base + j] = lo;
    }
}

// ---------------- bf16x2 tensor-core GEMM on pre-packed operands ----------------
// C = act(A[M,K] @ B[N,K]^T + bias); A,B packed hi/lo bf16 planes (pair words along k).
// Fragment loads via ldmatrix (stride-20 rows -> conflict-free, 16B-aligned).
// EPI: 0 = fp32 out (Cf), 1 = packed hi/lo out (Cp), 2 = QKV column-split into g_Qb/g_Kb/g_Vb.
template <int TM, int TN, int WM, int WN, bool SWISH, int EPI>
__global__ void __launch_bounds__(WM * WN * 32, (WM * WN * 32 >= 256) ? 2 : 4)
k_tgemm(const unsigned* __restrict__ Ah, const unsigned* __restrict__ Bh,
        const float* __restrict__ bias,
        float* __restrict__ Cf, unsigned* __restrict__ Cp,
        int M, int Nn, int Kw, int ldaw, int ldbw,
        long long plA, long long plB, long long plC,
        long long sA_, long long sB_, long long sBias, long long sC) {
    constexpr int THREADS = WM * WN * 32;
    constexpr int MT = TM / WM / 16;
    constexpr int NT = TN / WN / 8;
    constexpr int WS = 20;

    __shared__ __align__(16) unsigned shA[2][TM * WS];
    __shared__ __align__(16) unsigned shB[2][TN * WS];

    int z = blockIdx.z;
    const unsigned* Al = Ah + plA + (long long)z * sA_;
    const unsigned* Bl = Bh + plB + (long long)z * sB_;
    Ah += (long long)z * sA_;
    Bh += (long long)z * sB_;
    if (Cf) Cf += (long long)z * sC;
    if (Cp) Cp += (long long)z * sC;
    const float* bptr = bias ? bias + (long long)z * sBias : nullptr;

    int tid = threadIdx.x;
    int m0 = blockIdx.y * TM, n0 = blockIdx.x * TN;
    int wid = tid >> 5, lane = tid & 31;
    int wm = wid / WN, wn = wid % WN;
    int g = lane >> 2, tg = lane & 3;

    float acc[MT][NT][4];
#pragma unroll
    for (int mt = 0; mt < MT; mt++)
#pragma unroll
        for (int nt = 0; nt < NT; nt++)
#pragma unroll
            for (int i = 0; i < 4; i++) acc[mt][nt][i] = 0.f;

    int nK = Kw / 8;   // k16 steps

    auto load = [&](int k0w, int b) {
#pragma unroll 2
        for (int qi = tid; qi < TM * 4; qi += THREADS) {
            int r = qi >> 2, q = qi & 3;               // q<2: hi half0/1, q>=2: lo
            int gm = m0 + r;
            const unsigned* src = (q < 2) ? Ah : Al;
            uint4 v = make_uint4(0u, 0u, 0u, 0u);
            if (gm < M)
                v = *(const uint4*)(src + (long long)gm * ldaw + k0w + ((q & 1) << 2));
            *(uint4*)&shA[b][r * WS + ((q >= 2) ? 8 : 0) + ((q & 1) << 2)] = v;
        }
#pragma unroll 2
        for (int qi = tid; qi < TN * 4; qi += THREADS) {
            int r = qi >> 2, q = qi & 3;
            int gn = n0 + r;
            const unsigned* src = (q < 2) ? Bh : Bl;
            uint4 v = make_uint4(0u, 0u, 0u, 0u);
            if (gn < Nn)
                v = *(const uint4*)(src + (long long)gn * ldbw + k0w + ((q & 1) << 2));
            *(uint4*)&shB[b][r * WS + ((q >= 2) ? 8 : 0) + ((q & 1) << 2)] = v;
        }
    };

    // per-lane ldmatrix address offsets (within a tile), constant across iters
    int sub = lane >> 3, r8 = lane & 7;
    unsigned aOff = ((((sub & 1) << 3) + r8) * WS + ((sub >> 1) << 2)) * 4u;
    int l15 = lane & 15;
    unsigned bOff = (((l15 & 7) * WS) + ((l15 >> 3) << 2)) * 4u;

    auto compute = [&](int b) {
        unsigned aB = (unsigned)__cvta_generic_to_shared(&shA[b][0])
                      + (unsigned)((wm * MT * 16) * WS * 4) + aOff;
        unsigned bB = (unsigned)__cvta_generic_to_shared(&shB[b][0])
                      + (unsigned)((wn * NT * 8) * WS * 4) + bOff;
        unsigned bhi[NT][2], blo[NT][2];
#pragma unroll
        for (int nt = 0; nt < NT; nt++) {
            unsigned ad = bB + (unsigned)(nt * 8 * WS * 4);
            ldsm2(bhi[nt][0], bhi[nt][1], ad);
            ldsm2(blo[nt][0], blo[nt][1], ad + 32u);
        }
#pragma unroll
        for (int mt = 0; mt < MT; mt++) {
            unsigned ad = aB + (unsigned)(mt * 16 * WS * 4);
            unsigned ahi[4], alo[4];
            ldsm4(ahi[0], ahi[1], ahi[2], ahi[3], ad);
            ldsm4(alo[0], alo[1], alo[2], alo[3], ad + 32u);
#pragma unroll
            for (int nt = 0; nt < NT; nt++) {
                mma16(acc[mt][nt], ahi, bhi[nt]);
                mma16(acc[mt][nt], ahi, blo[nt]);
                mma16(acc[mt][nt], alo, bhi[nt]);
            }
        }
    };

    load(0, 0);
    __syncthreads();
    int buf = 0;
    for (int it = 0; it < nK; it++) {
        if (it + 1 < nK) load((it + 1) * 8, buf ^ 1);
        compute(buf);
        __syncthreads();
        buf ^= 1;
    }

    // epilogue: acc i=0:(g,2tg) i=1:(g,2tg+1) i=2:(g+8,2tg) i=3:(g+8,2tg+1)
#pragma unroll
    for (int mt = 0; mt < MT; mt++) {
        int r0 = m0 + (wm * MT + mt) * 16;
#pragma unroll
        for (int nt = 0; nt < NT; nt++) {
            int gn0 = n0 + (wn * NT + nt) * 8 + 2 * tg;
            if constexpr (EPI == 1) {
                float b0 = bptr ? bptr[gn0] : 0.f;
                float b1 = bptr ? bptr[gn0 + 1] : 0.f;
                int ldcw = Nn >> 1;
                long long wj = (gn0 >> 1);
#pragma unroll
                for (int half = 0; half < 2; half++) {
                    int gm = r0 + g + half * 8;
                    if (gm < M && gn0 + 1 < Nn) {
                        float v0 = acc[mt][nt][2 * half]     + b0;
                        float v1 = acc[mt][nt][2 * half + 1] + b1;
                        if (SWISH) { v0 = swishf(v0); v1 = swishf(v1); }
                        unsigned hi, lo;
                        pack2(v0, v1, hi, lo);
                        long long o = (long long)gm * ldcw + wj;
                        Cp[o] = hi;
                        Cp[o + plC] = lo;
                    }
                }
            } else if constexpr (EPI == 2) {
                int sel = gn0 >> 8;            // uniform per 128-wide tile
                int cc0 = gn0 & 255;
                float* dst = (sel == 0) ? g_Qb : (sel == 1) ? g_Kb : g_Vb;
#pragma unroll
                for (int i = 0; i < 4; i++) {
                    int gm = r0 + g + (i >> 1) * 8;
                    int cc = cc0 + (i & 1);
                    if (gm < M)
                        dst[((long long)z * cBA + gm) * cHID + cc] = acc[mt][nt][i];
                }
            } else {
#pragma unroll
                for (int i = 0; i < 4; i++) {
                    int gm = r0 + g + (i >> 1) * 8;
                    int gn = gn0 + (i & 1);
                    if (gm < M && gn < Nn) {
                        float v = acc[mt][nt][i] + (bptr ? bptr[gn] : 0.f);
                        if (SWISH) v = swishf(v);
                        Cf[(long long)gm * Nn + gn] = v;
                    }
                }
            }
        }
    }
}

// ---------------- split-K reduce for comp1 -> packed c1 ----------------
__global__ void k_redP(const float* __restrict__ part, const float* __restrict__ bias) {
    long long i = (long long)blockIdx.x * 256 + threadIdx.x;   // word index
    if (i >= P_C1) return;
    const long long MN = (long long)cBA * 2 * cHID;
    int j = (int)(i % (cHID));
    long long e = 2 * i;
    float s0 = part[e]     + part[e + MN]     + part[e + 2 * MN]     + part[e + 3 * MN]     + bias[2 * j];
    float s1 = part[e + 1] + part[e + 1 + MN] + part[e + 1 + 2 * MN] + part[e + 1 + 3 * MN] + bias[2 * j + 1];
    unsigned hi, lo;
    pack2(swishf(s0), swishf(s1), hi, lo);
    g_c1P[i] = hi;
    g_c1P[P_C1 + i] = lo;
}

// ---------------- 3. pad slots -> packed pad_token rows in eP ----------------
__global__ void k_padfixP(const float* __restrict__ pad_token) {
    int ba = blockIdx.x;
    int j = threadIdx.x;
    int cnt = g_cnt[ba];
    unsigned hi, lo;
    pack2(pad_token[2 * j], pad_token[2 * j + 1], hi, lo);
    for (int s = cnt; s < cE; s++) {
        long long o = ((long long)ba * cE + s) * (cHID / 2) + j;
        g_eP[o] = hi;
        g_eP[P_E + o] = lo;
    }
}

// ---------------- 4. attention: scores + softmax + alpha@V + swish -> packed Hs ----------------
__global__ void k_attn(const float* __restrict__ conn) {
    int gid = blockIdx.x;
    int a = gid % cA;
    int nb = gid / cA;
    int b = nb % cB, n = nb / cB;
    long long base = (((long long)n * cB + b) * cA) * cHID;
    const float* Qr = g_Qb + base + (long long)a * cHID;
    const float* Kb = g_Kb + base;
    const float* Vb = g_Vb + base;

    __shared__ float sQ[cHID];
    __shared__ float sAl[cA];
    __shared__ float sred[8];
    __shared__ float sstat;

    int tid = threadIdx.x, lane = tid & 31, w = tid >> 5;
    sQ[tid] = Qr[tid];
    __syncthreads();

    for (int c = w; c < cA; c += 8) {
        const float* Kr = Kb + (long long)c * cHID;
        float p = 0.f;
#pragma unroll
        for (int i = lane; i < cHID; i += 32) p += sQ[i] * Kr[i];
        p = warpSum(p);
        if (lane == 0) sAl[c] = p * 0.0625f + conn[a * cA + c];
    }
    __syncthreads();

    float mval = -1e30f;
    for (int c = tid; c < cA; c += 256) mval = fmaxf(mval, sAl[c]);
    mval = warpMax(mval);
    if (lane == 0) sred[w] = mval;
    __syncthreads();
    if (tid == 0) {
        float mm = -1e30f;
#pragma unroll
        for (int i = 0; i < 8; i++) mm = fmaxf(mm, sred[i]);
        sstat = mm;
    }
    __syncthreads();
    float gmax = sstat;
    float psum = 0.f;
    for (int c = tid; c < cA; c += 256) {
        float ev = expf(sAl[c] - gmax);
        sAl[c] = ev;
        psum += ev;
    }
    psum = warpSum(psum);
    __syncthreads();
    if (lane == 0) sred[w] = psum;
    __syncthreads();
    if (tid == 0) {
        float tot = 0.f;
#pragma unroll
        for (int i = 0; i < 8; i++) tot += sred[i];
        sstat = tot;
    }
    __syncthreads();
    float inv = 1.f / sstat;

    float acc = 0.f;
#pragma unroll 4
    for (int c = 0; c < cA; c++) acc += sAl[c] * Vb[(long long)c * cHID + tid];
    float v = swishf(acc * inv);

    unsigned h16, l16;
    split1(v, h16, l16);
    unsigned ho = __shfl_down_sync(0xffffffffu, h16, 1);
    unsigned lo = __shfl_down_sync(0xffffffffu, l16, 1);
    if (!(tid & 1)) {
        long long rb = ((((long long)n * cB + b) * cA) + a) * (cHID / 2) + (tid >> 1);
        g_HsP[rb] = (ho << 16) | h16;
        g_HsP[P_HS + rb] = (lo << 16) | l16;
    }
}

// ---------------- 5. layernorm per head + mean over heads -> packed h ----------------
__global__ void k_ln(const float* __restrict__ lnG, const float* __restrict__ lnB) {
    int m = blockIdx.x;
    int tid = threadIdx.x, lane = tid & 31, w = tid >> 5;
    __shared__ float sred[8];
    __shared__ float sval;
    float hacc = 0.f;
    for (int n = 0; n < cNH; n++) {
        float t = g_t2[((long long)n * cBA + m) * cHID + tid];
        float s = warpSum(t);
        if (lane == 0) sred[w] = s;
        __syncthreads();
        if (tid == 0) {
            float tot = 0.f;
#pragma unroll
            for (int i = 0; i < 8; i++) tot += sred[i];
            sval = tot * (1.f / cHID);
        }
        __syncthreads();
        float mean = sval;
        float d = t - mean;
        float s2 = warpSum(d * d);
        __syncthreads();
        if (lane == 0) sred[w] = s2;
        __syncthreads();
        if (tid == 0) {
            float tot = 0.f;
#pragma unroll
            for (int i = 0; i < 8; i++) tot += sred[i];
            sval = rsqrtf(tot * (1.f / cHID) + 1e-5f);
        }
        __syncthreads();
        hacc += d * sval * lnG[n * cHID + tid] + lnB[n * cHID + tid];
        __syncthreads();
    }
    float v = hacc * 0.25f;
    unsigned h16, l16;
    split1(v, h16, l16);
    unsigned ho = __shfl_down_sync(0xffffffffu, h16, 1);
    unsigned lo = __shfl_down_sync(0xffffffffu, l16, 1);
    if (!(tid & 1)) {
        long long rb = (long long)m * (cHID / 2) + (tid >> 1);
        g_hP[rb] = (ho << 16) | h16;
        g_hP[P_H + rb] = (lo << 16) | l16;
    }
}

// ---------------- host-side launch helper ----------------
template <int TM, int TN, int WM, int WN, bool SW, int EPI>
static void tg(const unsigned* Ah, const unsigned* Bh, const float* bias,
               float* Cf, unsigned* Cp,
               int M, int N, int Kw, int ldaw, int ldbw,
               long long plA, long long plB, long long plC,
               long long sA = 0, long long sB = 0, long long sb = 0, long long sC = 0,
               int batch = 1) {
    dim3 grid((N + TN - 1) / TN, (M + TM - 1) / TM, batch);
    k_tgemm<TM, TN, WM, WN, SW, EPI><<<grid, WM * WN * 32>>>(
        Ah, Bh, bias, Cf, Cp, M, N, Kw, ldaw, ldbw, plA, plB, plC, sA, sB, sb, sC);
}

extern "C" void kernel_launch(void* const* d_in, const int* in_sizes, int n_in,
                              void* d_out, int out_size) {
    const float* x       = (const float*)d_in[0];
    const float* fourier = (const float*)d_in[1];
    const float* encW1   = (const float*)d_in[2];
    const float* encB1   = (const float*)d_in[3];
    const float* encW2   = (const float*)d_in[4];
    const float* encB2   = (const float*)d_in[5];
    const float* padTok  = (const float*)d_in[6];
    const float* compW1  = (const float*)d_in[7];
    const float* compB1  = (const float*)d_in[8];
    const float* compW2  = (const float*)d_in[9];
    const float* compB2  = (const float*)d_in[10];
    const float* conn    = (const float*)d_in[11];
    const float* qW      = (const float*)d_in[12];
    const float* kW      = (const float*)d_in[13];
    const float* vW      = (const float*)d_in[14];
    const float* fpW1    = (const float*)d_in[15];
    const float* fpB1    = (const float*)d_in[16];
    const float* fpW2    = (const float*)d_in[17];
    const float* fpB2    = (const float*)d_in[18];
    const float* lnG     = (const float*)d_in[19];
    const float* lnB     = (const float*)d_in[20];
    const float* outW    = (const float*)d_in[21];
    const float* outB    = (const float*)d_in[22];
    float* out = (float*)d_out;

    unsigned *pFeatP, *pH1P, *pEP, *pC1P, *pHP, *pHsP, *pT1P;
    unsigned *pW1, *pW2, *pCW1, *pCW2, *pQKVW, *pF1W, *pF2W, *pOW;
    float *pCK, *pT2;
    cudaGetSymbolAddress((void**)&pFeatP, g_featP);
    cudaGetSymbolAddress((void**)&pH1P,   g_H1P);
    cudaGetSymbolAddress((void**)&pEP,    g_eP);
    cudaGetSymbolAddress((void**)&pC1P,   g_c1P);
    cudaGetSymbolAddress((void**)&pHP,    g_hP);
    cudaGetSymbolAddress((void**)&pHsP,   g_HsP);
    cudaGetSymbolAddress((void**)&pT1P,   g_t1P);
    cudaGetSymbolAddress((void**)&pW1,    g_encW1P);
    cudaGetSymbolAddress((void**)&pW2,    g_encW2P);
    cudaGetSymbolAddress((void**)&pCW1,   g_compW1P);
    cudaGetSymbolAddress((void**)&pCW2,   g_compW2P);
    cudaGetSymbolAddress((void**)&pQKVW,  g_qkvWP);
    cudaGetSymbolAddress((void**)&pF1W,   g_fp1WP);
    cudaGetSymbolAddress((void**)&pF2W,   g_fp2WP);
    cudaGetSymbolAddress((void**)&pOW,    g_outWP);
    cudaGetSymbolAddress((void**)&pCK,    g_ck);
    cudaGetSymbolAddress((void**)&pT2,    g_t2);

    auto packW = [&](const float* W, unsigned* P, int rows, int Kin, int KoutW) {
        long long tot = (long long)rows * KoutW;
        k_pack<<<(unsigned)((tot + 255) / 256), 256>>>(W, P, rows, Kin, KoutW, tot);
    };

    // ordered so launch #6 (ncu -s 5 -c 1) is the big enc2 GEMM
    k_gather<<<cBA, 256>>>(x);                                    // 1
    k_featP<<<(cSLOTS + 255) / 256, 256>>>(fourier);              // 2
    packW(encW1, pW1, 256, cFEAT, cFP / 2);                       // 3
    packW(encW2, pW2, 256, 256, 128);                             // 4
    tg<128,128,2,4,true ,1>(pFeatP, pW1, encB1, nullptr, pH1P,    // 5
        cSLOTS, cHID, cFP / 2, cFP / 2, cFP / 2, P_FEAT, (long long)256 * (cFP / 2), P_H1);
    tg<128,128,2,4,false,1>(pH1P, pW2, encB2, nullptr, pEP,       // 6 <- profiled
        cSLOTS, cHID, 128, 128, 128, P_H1, 256 * 128, P_E);
    k_padfixP<<<cBA, 128>>>(padTok);

    // per-agent compression: split-K=4 partials (fp32) + fused packed reduce
    packW(compW1, pCW1, 512, 25600, 12800);
    tg<128,128,2,4,false,0>(pEP, pCW1, nullptr, pCK, nullptr,
        cBA, 2 * cHID, cKCH / 2, 12800, 12800, P_E, (long long)512 * 12800, 0,
        /*sA=*/cKCH / 2, /*sB=*/cKCH / 2, 0, /*sC=*/(long long)cBA * 2 * cHID, cKS);
    k_redP<<<(unsigned)((P_C1 + 255) / 256), 256>>>(pCK, compB1);
    packW(compW2, pCW2, 256, 512, 256);
    tg<64,64,2,2,false,1>(pC1P, pCW2, compB2, nullptr, pHP,
        cBA, cHID, 256, 256, 256, P_C1, (long long)256 * 256, P_H);

    // remaining weight packs
    k_packQKV<<<(unsigned)((PL_QKV + 255) / 256), 256>>>(qW, kW, vW, pQKVW);
    packW(fpW1, pF1W, 1024, 256, 128);
    packW(fpW2, pF2W, 1024, 256, 128);
    packW(outW, pOW,  cOUT, 256, 128);

    // message passing
    const long long sWw = (long long)cHID * 128;   // per-head weight stride (words)
    const long long sMf = (long long)cBA * cHID;   // per-head fp32 act stride (elements)
    const long long sMw = (long long)cBA * 128;    // per-head packed act stride (words)
    for (int s = 0; s < cSTEPS; s++) {
        // fused QKV: N=768 columns split into Q/K/V inside the epilogue
        tg<128,128,2,4,false,2>(pHP, pQKVW, nullptr, nullptr, nullptr,
            cBA, 768, 128, 128, 128, P_H, PL_QKV, 0, 0, (long long)768 * 128, 0, 0, cNH);
        k_attn<<<cNH * cBA, 256>>>(conn);
        tg<128,128,2,4,true ,1>(pHsP, pF1W, fpB1, nullptr, pT1P,
            cBA, cHID, 128, 128, 128, P_HS, (long long)1024 * 128, P_T1,
            sMw, sWw, cHID, sMw, cNH);
        tg<128,128,2,4,false,0>(pT1P, pF2W, fpB2, pT2, nullptr,
            cBA, cHID, 128, 128, 128, P_T1, (long long)1024 * 128, 0,
            sMw, sWw, cHID, sMf, cNH);
        k_ln<<<cBA, 256>>>(lnG, lnB);
    }

    // output projection
    tg<128,128,2,4,false,0>(pHP, pOW, outB, out, nullptr,
        cBA, cOUT, 128, 128, 128, P_H, (long long)cOUT * 128, 0);
}